// round 12
// baseline (speedup 1.0000x reference)
#include <cuda_runtime.h>
#include <cstdint>

typedef unsigned long long ull;

#define BB 64
#define NN 16
#define TT 128
#define HH 256
#define NP1 17
#define NPAIRS (BB*NP1)   // 1088
#define LDT 132           // padded smem row stride for SIMT kernels

// ---------------- scratch (static device globals; no runtime allocation) ----------------
__device__ float g_q  [BB*TT*HH];
__device__ float g_t2 [BB*TT*HH];
__device__ float g_P  [BB*TT*HH];
__device__ float g_Afb[(size_t)NPAIRS*TT*TT];

// =================== PTX helpers (baseline ISA — no tcgen05 on sm_103 target) ===========
__device__ __forceinline__ uint32_t smem_u32(const void* p){
    uint32_t a;
    asm("{ .reg .u64 t; cvta.to.shared.u64 t, %1; cvt.u32.u64 %0, t; }" : "=r"(a) : "l"(p));
    return a;
}
// pack_bf(a,b): 32-bit word, low16 = bf16(a), high16 = bf16(b)
__device__ __forceinline__ uint32_t pack_bf(float a, float b){
    uint32_t r;
    asm("cvt.rn.satfinite.bf16x2.f32 %0, %1, %2;" : "=r"(r) : "f"(b), "f"(a));
    return r;
}
__device__ __forceinline__ void ldsm4(uint32_t r[4], uint32_t addr){
    asm volatile("ldmatrix.sync.aligned.m8n8.x4.shared.b16 {%0,%1,%2,%3}, [%4];"
        : "=r"(r[0]), "=r"(r[1]), "=r"(r[2]), "=r"(r[3]) : "r"(addr));
}
__device__ __forceinline__ void mma_bf16(float c[4], const uint32_t a[4],
                                         uint32_t b0, uint32_t b1){
    asm volatile(
        "mma.sync.aligned.m16n8k16.row.col.f32.bf16.bf16.f32 "
        "{%0,%1,%2,%3}, {%4,%5,%6,%7}, {%8,%9}, {%0,%1,%2,%3};"
        : "+f"(c[0]), "+f"(c[1]), "+f"(c[2]), "+f"(c[3])
        : "r"(a[0]), "r"(a[1]), "r"(a[2]), "r"(a[3]), "r"(b0), "r"(b1));
}

// convert a [128 rows x 64 cols] fp32 tile into (hi, lo) bf16 swizzled tiles.
// tile layout: byte = row*128 + col*2, XOR-swizzled by ((row&7)<<4) -> conflict-free ldmatrix.
__device__ __forceinline__ void cvt_tile(char* th, char* tl, const float* __restrict__ src,
                                         int ld, int tid){
    int row = tid >> 1;
    int c0  = (tid & 1) * 32;
    const float* s = src + (size_t)row*ld + c0;
    #pragma unroll
    for (int j = 0; j < 8; ++j){
        float4 v = *(const float4*)(s + j*4);
        uint32_t h0 = pack_bf(v.x, v.y), h1 = pack_bf(v.z, v.w);
        float lx = v.x - __uint_as_float(h0 << 16);
        float ly = v.y - __uint_as_float(h0 & 0xffff0000u);
        float lz = v.z - __uint_as_float(h1 << 16);
        float lw = v.w - __uint_as_float(h1 & 0xffff0000u);
        uint32_t l0 = pack_bf(lx, ly), l1 = pack_bf(lz, lw);
        uint32_t boff = (uint32_t)row*128u + (uint32_t)(c0 + j*4)*2u;
        uint32_t sw = boff ^ ((boff >> 3) & 0x70u);
        *(ull*)(th + sw) = (ull)h0 | ((ull)h1 << 32);
        *(ull*)(tl + sw) = (ull)l0 | ((ull)l1 << 32);
    }
}

__device__ __forceinline__ const float* pair_base(int p, const float* node, const float* neigh){
    int b = p / NP1, n = p % NP1;
    return (n == 0) ? node  + (size_t)b*TT*HH
                    : neigh + (size_t)(b*NN + (n-1))*TT*HH;
}

// ---------------- one K=64 slab of split MMAs, 2D warp tiling ----------------------------
// warp (mg, ng): rows [32*mg, 32*mg+32) as 2 m-tiles, cols [64*ng, 64*ng+64) as 8 n-tiles.
// acc[mt][nt][4]; n-tile nt covers cols 64*ng + nt*8 .. +7.
__device__ __forceinline__ void slab_mma_warp(float acc[2][8][4],
                                              uint32_t uAH, uint32_t uAL,
                                              uint32_t uBH, uint32_t uBL,
                                              int mg, int ng, int l){
    int r8 = l & 7;
    uint32_t swx  = (uint32_t)r8 << 4;
    uint32_t aKadd = ((l>>4)&1) * 16;             // +8 bf16 for A matrices 2,3
    int rowA0 = 32*mg + ((l>>3)&1)*8 + r8;
    int rowBl = ((l>>4)&1)*8 + r8;
    uint32_t bKadd = ((l>>3)&1) * 16;
    #pragma unroll
    for (int ks = 0; ks < 4; ++ks){
        uint32_t ah[2][4], al[2][4];
        #pragma unroll
        for (int mt = 0; mt < 2; ++mt){
            uint32_t aoff = (uint32_t)(rowA0 + 16*mt)*128u
                          + (((uint32_t)ks*32 + aKadd) ^ swx);
            ldsm4(ah[mt], uAH + aoff);
            ldsm4(al[mt], uAL + aoff);
        }
        uint32_t bkb = (uint32_t)ks*32 + bKadd;
        #pragma unroll
        for (int ntp = 0; ntp < 4; ++ntp){
            int rowB = ng*64 + ntp*16 + rowBl;
            uint32_t boff = (uint32_t)rowB*128u + (bkb ^ swx);
            uint32_t bh[4], bl[4];
            ldsm4(bh, uBH + boff);
            ldsm4(bl, uBL + boff);
            #pragma unroll
            for (int mt = 0; mt < 2; ++mt){
                mma_bf16(acc[mt][2*ntp],   ah[mt], bh[0], bh[1]);
                mma_bf16(acc[mt][2*ntp],   ah[mt], bl[0], bl[1]);
                mma_bf16(acc[mt][2*ntp],   al[mt], bh[0], bh[1]);
                mma_bf16(acc[mt][2*ntp+1], ah[mt], bh[2], bh[3]);
                mma_bf16(acc[mt][2*ntp+1], ah[mt], bl[2], bl[3]);
                mma_bf16(acc[mt][2*ntp+1], al[mt], bh[2], bh[3]);
            }
        }
    }
}

// =================== SIMT fp32 machinery (K1..K3 weight chain) ===========================
__device__ __forceinline__ void fma2(ull& d, ull a, ull b){
    asm("fma.rn.f32x2 %0, %1, %2, %0;" : "+l"(d) : "l"(a), "l"(b));
}
__device__ __forceinline__ ull pk2(float x, float y){
    ull r; asm("mov.b64 %0, {%1, %2};" : "=l"(r) : "f"(x), "f"(y)); return r;
}
__device__ __forceinline__ float2 upk(ull v){
    float2 f; asm("mov.b64 {%0, %1}, %2;" : "=f"(f.x), "=f"(f.y) : "l"(v)); return f;
}
struct F8 { float4 a, b; };
__device__ __forceinline__ F8 ldg_T(const float* __restrict__ src, int ld, int tid){
    int c4 = (tid & 3) * 4, r = tid >> 2;
    F8 f;
    f.a = *(const float4*)(src + (size_t)r*ld + c4);
    f.b = *(const float4*)(src + (size_t)(r+64)*ld + c4);
    return f;
}
__device__ __forceinline__ void sts_T(float (*dst)[LDT], F8 f, int tid){
    int c4 = (tid & 3) * 4, r = tid >> 2;
    dst[c4+0][r]    = f.a.x; dst[c4+1][r]    = f.a.y;
    dst[c4+2][r]    = f.a.z; dst[c4+3][r]    = f.a.w;
    dst[c4+0][r+64] = f.b.x; dst[c4+1][r+64] = f.b.y;
    dst[c4+2][r+64] = f.b.z; dst[c4+3][r+64] = f.b.w;
}
__device__ __forceinline__ F8 ldg_D(const float* __restrict__ src, int ld, int tid){
    int n4 = (tid & 15) * 4, k = tid >> 4;
    F8 f;
    f.a = *(const float4*)(src + (size_t)k*ld + n4);
    f.b = *(const float4*)(src + (size_t)k*ld + n4 + 64);
    return f;
}
__device__ __forceinline__ void sts_D(float (*dst)[LDT], F8 f, int tid){
    int n4 = (tid & 15) * 4, k = tid >> 4;
    *(float4*)(&dst[k][n4])      = f.a;
    *(float4*)(&dst[k][n4 + 64]) = f.b;
}
__device__ __forceinline__ void mm16(ull acc[8][4], const float (*As)[LDT],
                                     const float (*Bs)[LDT], int tx, int ty){
    #pragma unroll
    for (int k = 0; k < 16; ++k){
        float4 a0 = *(const float4*)(&As[k][ty*4]);
        float4 a1 = *(const float4*)(&As[k][64+ty*4]);
        float4 b0 = *(const float4*)(&Bs[k][tx*4]);
        float4 b1 = *(const float4*)(&Bs[k][64+tx*4]);
        ull bb0 = pk2(b0.x,b0.y), bb1 = pk2(b0.z,b0.w);
        ull bb2 = pk2(b1.x,b1.y), bb3 = pk2(b1.z,b1.w);
        float av[8] = {a0.x,a0.y,a0.z,a0.w,a1.x,a1.y,a1.z,a1.w};
        #pragma unroll
        for (int i = 0; i < 8; ++i){
            ull ad = pk2(av[i], av[i]);
            fma2(acc[i][0], ad, bb0);
            fma2(acc[i][1], ad, bb1);
            fma2(acc[i][2], ad, bb2);
            fma2(acc[i][3], ad, bb3);
        }
    }
}
__device__ __forceinline__ int row_of(int i, int ty){
    return (i < 4) ? (ty*4 + i) : (64 + ty*4 + (i-4));
}

// ================= K1..K3: flat [8192,256] x [256,256] GEMM chain (SIMT) =================
template<int STEP>
__global__ void __launch_bounds__(256, 2) sgemm_flat(const float* __restrict__ Ain,
                                                     const float* __restrict__ W){
    __shared__ __align__(16) float As[2][16][LDT], Bs[2][16][LDT];
    int tid = threadIdx.x, tx = tid & 15, ty = tid >> 4;
    const float* A = (STEP == 0) ? Ain : (STEP == 1 ? g_q : g_t2);
    float*       C = (STEP == 0) ? g_q : (STEP == 1 ? g_t2 : g_P);
    const float* Ab = A + (size_t)blockIdx.x * 128 * HH;
    int n0 = blockIdx.y * 128;
    const float* Bb = (STEP == 0) ? W + (size_t)n0*HH : W + n0;

    ull acc[8][4];
    #pragma unroll
    for (int i=0;i<8;i++){ acc[i][0]=acc[i][1]=acc[i][2]=acc[i][3]=0ULL; }

    F8 ra = ldg_T(Ab, HH, tid);
    F8 rb = (STEP == 0) ? ldg_T(Bb, HH, tid) : ldg_D(Bb, HH, tid);
    sts_T(As[0], ra, tid);
    if (STEP == 0) sts_T(Bs[0], rb, tid); else sts_D(Bs[0], rb, tid);
    __syncthreads();

    #pragma unroll 2
    for (int s = 0; s < 16; ++s){
        if (s < 15){
            ra = ldg_T(Ab + (s+1)*16, HH, tid);
            rb = (STEP == 0) ? ldg_T(Bb + (s+1)*16, HH, tid)
                             : ldg_D(Bb + (size_t)(s+1)*16*HH, HH, tid);
        }
        mm16(acc, As[s&1], Bs[s&1], tx, ty);
        if (s < 15){
            sts_T(As[(s+1)&1], ra, tid);
            if (STEP == 0) sts_T(Bs[(s+1)&1], rb, tid); else sts_D(Bs[(s+1)&1], rb, tid);
        }
        __syncthreads();
    }

    float* Cb = C + (size_t)blockIdx.x*128*HH + n0;
    #pragma unroll
    for (int i=0;i<8;i++){
        int row = row_of(i, ty);
        float2 p0=upk(acc[i][0]), p1=upk(acc[i][1]), p2=upk(acc[i][2]), p3=upk(acc[i][3]);
        *(float4*)(Cb + (size_t)row*HH + tx*4)      = make_float4(p0.x,p0.y,p1.x,p1.y);
        *(float4*)(Cb + (size_t)row*HH + 64 + tx*4) = make_float4(p2.x,p2.y,p3.x,p3.y);
    }
}

// ================= K4 (tensor): S = P_b @ X_p^T (+bias) -> softmax -> A ==================
__global__ void __launch_bounds__(256) kernel_S_tc(const float* __restrict__ node,
                                                   const float* __restrict__ neigh,
                                                   const float* __restrict__ bias,
                                                   float* Aout){
    extern __shared__ char sm[];
    char* base = (char*)(((uintptr_t)sm + 1023) & ~(uintptr_t)1023);
    char* tPH = base;            char* tPL = base + 16384;
    char* tXH = base + 32768;    char* tXL = base + 49152;
    float* xchM = (float*)(base + 65536);        // [2][128]
    float* xchS = xchM + 256;                    // [2][128]
    uint32_t uPH = smem_u32(tPH), uPL = smem_u32(tPL);
    uint32_t uXH = smem_u32(tXH), uXL = smem_u32(tXL);

    int tid = threadIdx.x, w = tid >> 5, l = tid & 31;
    int mg = w >> 1, ng = w & 1;
    int p = blockIdx.x, b = p / NP1;
    const float* P = g_P + (size_t)b*TT*HH;
    const float* X = pair_base(p, node, neigh);
    float* Ao = Aout ? Aout : g_Afb;

    float acc[2][8][4];
    #pragma unroll
    for (int i=0;i<2;i++)
        #pragma unroll
        for (int j=0;j<8;j++){ acc[i][j][0]=acc[i][j][1]=acc[i][j][2]=acc[i][j][3]=0.f; }

    for (int s = 0; s < 4; ++s){
        cvt_tile(tPH, tPL, P + s*64, HH, tid);
        cvt_tile(tXH, tXL, X + s*64, HH, tid);
        __syncthreads();
        slab_mma_warp(acc, uPH, uPL, uXH, uXL, mg, ng, l);
        __syncthreads();
    }

    // epilogue: lane owns rows r(mt,hf) = 32mg + 16mt + 8hf + (l>>2),
    // cols 64ng + nt*8 + q*2 (+1). Softmax over full 128 cols -> combine ng pair via smem.
    int q = l & 3, rb = l >> 2;

    #pragma unroll
    for (int nt = 0; nt < 8; ++nt){
        float2 bb = *(const float2*)(bias + ng*64 + nt*8 + q*2);
        #pragma unroll
        for (int mt = 0; mt < 2; ++mt){
            acc[mt][nt][0] += bb.x; acc[mt][nt][1] += bb.y;
            acc[mt][nt][2] += bb.x; acc[mt][nt][3] += bb.y;
        }
    }
    float mx[2][2];
    #pragma unroll
    for (int mt = 0; mt < 2; ++mt){
        mx[mt][0] = -1e30f; mx[mt][1] = -1e30f;
        #pragma unroll
        for (int nt = 0; nt < 8; ++nt){
            mx[mt][0] = fmaxf(mx[mt][0], fmaxf(acc[mt][nt][0], acc[mt][nt][1]));
            mx[mt][1] = fmaxf(mx[mt][1], fmaxf(acc[mt][nt][2], acc[mt][nt][3]));
        }
        #pragma unroll
        for (int o = 1; o <= 2; o <<= 1){
            mx[mt][0] = fmaxf(mx[mt][0], __shfl_xor_sync(0xffffffffu, mx[mt][0], o));
            mx[mt][1] = fmaxf(mx[mt][1], __shfl_xor_sync(0xffffffffu, mx[mt][1], o));
        }
    }
    if (q == 0){
        #pragma unroll
        for (int mt = 0; mt < 2; ++mt){
            xchM[ng*128 + 32*mg + 16*mt + rb]     = mx[mt][0];
            xchM[ng*128 + 32*mg + 16*mt + 8 + rb] = mx[mt][1];
        }
    }
    __syncthreads();
    float sum[2][2];
    #pragma unroll
    for (int mt = 0; mt < 2; ++mt){
        int r0 = 32*mg + 16*mt + rb;
        float m0 = fmaxf(xchM[r0],     xchM[128 + r0]);
        float m1 = fmaxf(xchM[r0 + 8], xchM[128 + r0 + 8]);
        sum[mt][0] = 0.f; sum[mt][1] = 0.f;
        #pragma unroll
        for (int nt = 0; nt < 8; ++nt){
            acc[mt][nt][0] = __expf(acc[mt][nt][0] - m0); sum[mt][0] += acc[mt][nt][0];
            acc[mt][nt][1] = __expf(acc[mt][nt][1] - m0); sum[mt][0] += acc[mt][nt][1];
            acc[mt][nt][2] = __expf(acc[mt][nt][2] - m1); sum[mt][1] += acc[mt][nt][2];
            acc[mt][nt][3] = __expf(acc[mt][nt][3] - m1); sum[mt][1] += acc[mt][nt][3];
        }
        #pragma unroll
        for (int o = 1; o <= 2; o <<= 1){
            sum[mt][0] += __shfl_xor_sync(0xffffffffu, sum[mt][0], o);
            sum[mt][1] += __shfl_xor_sync(0xffffffffu, sum[mt][1], o);
        }
    }
    if (q == 0){
        #pragma unroll
        for (int mt = 0; mt < 2; ++mt){
            xchS[ng*128 + 32*mg + 16*mt + rb]     = sum[mt][0];
            xchS[ng*128 + 32*mg + 16*mt + 8 + rb] = sum[mt][1];
        }
    }
    __syncthreads();
    float* Ap = Ao + (size_t)p*TT*TT;
    #pragma unroll
    for (int mt = 0; mt < 2; ++mt){
        int r0 = 32*mg + 16*mt + rb, r1 = r0 + 8;
        float i0 = 1.f / (xchS[r0] + xchS[128 + r0]);
        float i1 = 1.f / (xchS[r1] + xchS[128 + r1]);
        #pragma unroll
        for (int nt = 0; nt < 8; ++nt){
            *(float2*)(Ap + (size_t)r0*TT + ng*64 + nt*8 + q*2) =
                make_float2(acc[mt][nt][0]*i0, acc[mt][nt][1]*i0);
            *(float2*)(Ap + (size_t)r1*TT + ng*64 + nt*8 + q*2) =
                make_float2(acc[mt][nt][2]*i1, acc[mt][nt][3]*i1);
        }
    }
}

// ================= K5 (tensor): Vt[c,s] = Wv_chunk @ X^T ; O = A @ Vt^T ==================
__global__ void __launch_bounds__(256) kernel_VO_tc(const float* __restrict__ node,
                                                    const float* __restrict__ neigh,
                                                    const float* __restrict__ Wv,
                                                    const float* Ain,
                                                    float* __restrict__ Out){
    extern __shared__ char sm[];
    char* base = (char*)(((uintptr_t)sm + 1023) & ~(uintptr_t)1023);
    char* T0 = base;          char* T1 = base + 16384;
    char* T2 = base + 32768;  char* T3 = base + 49152;
    char* T4 = base + 65536;  char* T5 = base + 81920;
    uint32_t u0 = smem_u32(T0), u1 = smem_u32(T1), u2 = smem_u32(T2);
    uint32_t u3 = smem_u32(T3), u4 = smem_u32(T4), u5 = smem_u32(T5);

    int tid = threadIdx.x, w = tid >> 5, l = tid & 31;
    int mg = w >> 1, ng = w & 1;
    int p = blockIdx.x;
    int n0 = blockIdx.y * 128;
    const float* X  = pair_base(p, node, neigh);
    const float* Wc = Wv + (size_t)n0*HH;
    const float* Ap = (Ain ? Ain : (const float*)g_Afb) + (size_t)p*TT*TT;

    float acc[2][8][4];
    #pragma unroll
    for (int i=0;i<2;i++)
        #pragma unroll
        for (int j=0;j<8;j++){ acc[i][j][0]=acc[i][j][1]=acc[i][j][2]=acc[i][j][3]=0.f; }

    // ---- Phase 1: D1[c, s] = sum_h Wv[n0+c, h] * X[s, h] ----
    for (int s = 0; s < 4; ++s){
        cvt_tile(T0, T1, Wc + s*64, HH, tid);
        cvt_tile(T2, T3, X  + s*64, HH, tid);
        __syncthreads();
        slab_mma_warp(acc, u0, u1, u2, u3, mg, ng, l);
        __syncthreads();
    }

    // ---- Phase 2: split-convert D1 into persistent Vt tiles ----
    // Vt[c][s_local]: s-half 0 (ng==0) -> hi T0 / lo T1 ; s-half 1 (ng==1) -> T2 / T3
    {
        int q = l & 3, rb = l >> 2;
        char* th = ng ? T2 : T0;
        char* tl = ng ? T3 : T1;
        #pragma unroll
        for (int mt = 0; mt < 2; ++mt){
            #pragma unroll
            for (int hf = 0; hf < 2; ++hf){
                int c = 32*mg + 16*mt + 8*hf + rb;
                uint32_t swc = (uint32_t)(c & 7) << 4;
                #pragma unroll
                for (int nt = 0; nt < 8; ++nt){
                    int sl = nt*8 + q*2;
                    float a = acc[mt][nt][2*hf], bq = acc[mt][nt][2*hf+1];
                    uint32_t hi = pack_bf(a, bq);
                    float la = a  - __uint_as_float(hi << 16);
                    float lb = bq - __uint_as_float(hi & 0xffff0000u);
                    uint32_t lo = pack_bf(la, lb);
                    uint32_t boff = (uint32_t)c*128u + (uint32_t)sl*2u;
                    uint32_t swz = boff ^ swc;
                    *(uint32_t*)(th + swz) = hi;
                    *(uint32_t*)(tl + swz) = lo;
                }
            }
        }
        #pragma unroll
        for (int i=0;i<2;i++)
            #pragma unroll
            for (int j=0;j<8;j++){ acc[i][j][0]=acc[i][j][1]=acc[i][j][2]=acc[i][j][3]=0.f; }
    }
    __syncthreads();

    // ---- Phase 3: D2[t, c] = sum_s A[t, s] * Vt[c, s] ----
    for (int s2 = 0; s2 < 2; ++s2){
        cvt_tile(T4, T5, Ap + s2*64, TT, tid);
        __syncthreads();
        slab_mma_warp(acc, u4, u5, s2 ? u2 : u0, s2 ? u3 : u1, mg, ng, l);
        __syncthreads();
    }

    // ---- Phase 4: store O[t, n0 + c] ----
    {
        int q = l & 3, rb = l >> 2;
        float* Ob = Out + (size_t)p*TT*HH + n0;
        #pragma unroll
        for (int mt = 0; mt < 2; ++mt){
            int t0 = 32*mg + 16*mt + rb, t1 = t0 + 8;
            #pragma unroll
            for (int nt = 0; nt < 8; ++nt){
                *(float2*)(Ob + (size_t)t0*HH + ng*64 + nt*8 + q*2) =
                    make_float2(acc[mt][nt][0], acc[mt][nt][1]);
                *(float2*)(Ob + (size_t)t1*HH + ng*64 + nt*8 + q*2) =
                    make_float2(acc[mt][nt][2], acc[mt][nt][3]);
            }
        }
    }
}

// =========================================================================================
extern "C" void kernel_launch(void* const* d_in, const int* in_sizes, int n_in,
                              void* d_out, int out_size){
    const float* node  = (const float*)d_in[0];
    const float* neigh = (const float*)d_in[1];
    int w = (n_in >= 8) ? 2 : 1;
    const float* Wq = (const float*)d_in[w+1];
    const float* Wk = (const float*)d_in[w+2];
    const float* Wv = (const float*)d_in[w+3];
    const float* Wb = (const float*)d_in[w+4];
    const float* bv = (const float*)d_in[w+5];

    float* out = (float*)d_out;
    const long long O_ELEMS = (long long)NPAIRS*TT*HH;
    const long long A_ELEMS = (long long)NPAIRS*TT*TT;
    float* Aout = ((long long)out_size >= O_ELEMS + A_ELEMS) ? (out + O_ELEMS) : nullptr;

    const int S_SMEM  = 4*16384 + 2048 + 1024;   // 4 bf16 tiles + softmax xchg + align pad
    const int VO_SMEM = 6*16384 + 1024;          // 6 bf16 tiles + align pad
    cudaFuncSetAttribute(kernel_S_tc,  cudaFuncAttributeMaxDynamicSharedMemorySize, S_SMEM);
    cudaFuncSetAttribute(kernel_VO_tc, cudaFuncAttributeMaxDynamicSharedMemorySize, VO_SMEM);

    dim3 thr(256);
    sgemm_flat<0><<<dim3(64,2), thr>>>(node, Wq);        // g_q  = node @ Wq^T
    sgemm_flat<1><<<dim3(64,2), thr>>>(nullptr, Wb);     // g_t2 = g_q @ Wb
    sgemm_flat<2><<<dim3(64,2), thr>>>(nullptr, Wk);     // g_P  = g_t2 @ Wk
    kernel_S_tc <<<dim3(NPAIRS,1), thr, S_SMEM>>>(node, neigh, bv, Aout);
    kernel_VO_tc<<<dim3(NPAIRS,2), thr, VO_SMEM>>>(node, neigh, Wv, Aout, out);
}

// round 13
// speedup vs baseline: 1.1601x; 1.1601x over previous
#include <cuda_runtime.h>
#include <cstdint>

typedef unsigned long long ull;

#define BB 64
#define NN 16
#define TT 128
#define HH 256
#define NP1 17
#define NPAIRS (BB*NP1)   // 1088
#define LDT 132           // padded smem row stride for SIMT kernels

// ---------------- scratch (static device globals; no runtime allocation) ----------------
__device__ float g_q  [BB*TT*HH];
__device__ float g_t2 [BB*TT*HH];
__device__ float g_P  [BB*TT*HH];
__device__ float g_Afb[(size_t)NPAIRS*TT*TT];

// =================== PTX helpers (baseline ISA — no tcgen05 on sm_103 target) ===========
__device__ __forceinline__ uint32_t smem_u32(const void* p){
    uint32_t a;
    asm("{ .reg .u64 t; cvta.to.shared.u64 t, %1; cvt.u32.u64 %0, t; }" : "=r"(a) : "l"(p));
    return a;
}
// pack_bf(a,b): 32-bit word, low16 = bf16(a), high16 = bf16(b)
__device__ __forceinline__ uint32_t pack_bf(float a, float b){
    uint32_t r;
    asm("cvt.rn.satfinite.bf16x2.f32 %0, %1, %2;" : "=r"(r) : "f"(b), "f"(a));
    return r;
}
__device__ __forceinline__ void ldsm4(uint32_t r[4], uint32_t addr){
    asm volatile("ldmatrix.sync.aligned.m8n8.x4.shared.b16 {%0,%1,%2,%3}, [%4];"
        : "=r"(r[0]), "=r"(r[1]), "=r"(r[2]), "=r"(r[3]) : "r"(addr));
}
__device__ __forceinline__ void mma_bf16(float c[4], const uint32_t a[4],
                                         uint32_t b0, uint32_t b1){
    asm volatile(
        "mma.sync.aligned.m16n8k16.row.col.f32.bf16.bf16.f32 "
        "{%0,%1,%2,%3}, {%4,%5,%6,%7}, {%8,%9}, {%0,%1,%2,%3};"
        : "+f"(c[0]), "+f"(c[1]), "+f"(c[2]), "+f"(c[3])
        : "r"(a[0]), "r"(a[1]), "r"(a[2]), "r"(a[3]), "r"(b0), "r"(b1));
}

// convert a [128 rows x 64 cols] fp32 tile into (hi, lo) bf16 swizzled tiles.
// tile layout: byte = row*128 + col*2, XOR-swizzled by ((row&7)<<4) -> conflict-free ldmatrix.
__device__ __forceinline__ void cvt_tile(char* th, char* tl, const float* __restrict__ src,
                                         int ld, int tid){
    int row = tid >> 1;
    int c0  = (tid & 1) * 32;
    const float* s = src + (size_t)row*ld + c0;
    #pragma unroll
    for (int j = 0; j < 8; ++j){
        float4 v = *(const float4*)(s + j*4);
        uint32_t h0 = pack_bf(v.x, v.y), h1 = pack_bf(v.z, v.w);
        float lx = v.x - __uint_as_float(h0 << 16);
        float ly = v.y - __uint_as_float(h0 & 0xffff0000u);
        float lz = v.z - __uint_as_float(h1 << 16);
        float lw = v.w - __uint_as_float(h1 & 0xffff0000u);
        uint32_t l0 = pack_bf(lx, ly), l1 = pack_bf(lz, lw);
        uint32_t boff = (uint32_t)row*128u + (uint32_t)(c0 + j*4)*2u;
        uint32_t sw = boff ^ ((boff >> 3) & 0x70u);
        *(ull*)(th + sw) = (ull)h0 | ((ull)h1 << 32);
        *(ull*)(tl + sw) = (ull)l0 | ((ull)l1 << 32);
    }
}

__device__ __forceinline__ const float* pair_base(int p, const float* node, const float* neigh){
    int b = p / NP1, n = p % NP1;
    return (n == 0) ? node  + (size_t)b*TT*HH
                    : neigh + (size_t)(b*NN + (n-1))*TT*HH;
}

// ---------------- one K=64 slab of split MMAs, 2D warp tiling ----------------------------
// warp (mg, ng): rows [32*mg, 32*mg+32) as 2 m-tiles, cols [64*ng, 64*ng+64) as 8 n-tiles.
// acc[mt][nt][4]; n-tile nt covers cols 64*ng + nt*8 .. +7.
__device__ __forceinline__ void slab_mma_warp(float acc[2][8][4],
                                              uint32_t uAH, uint32_t uAL,
                                              uint32_t uBH, uint32_t uBL,
                                              int mg, int ng, int l){
    int r8 = l & 7;
    uint32_t swx  = (uint32_t)r8 << 4;
    uint32_t aKadd = ((l>>4)&1) * 16;             // +8 bf16 for A matrices 2,3
    int rowA0 = 32*mg + ((l>>3)&1)*8 + r8;
    int rowBl = ((l>>4)&1)*8 + r8;
    uint32_t bKadd = ((l>>3)&1) * 16;
    #pragma unroll
    for (int ks = 0; ks < 4; ++ks){
        uint32_t ah[2][4], al[2][4];
        #pragma unroll
        for (int mt = 0; mt < 2; ++mt){
            uint32_t aoff = (uint32_t)(rowA0 + 16*mt)*128u
                          + (((uint32_t)ks*32 + aKadd) ^ swx);
            ldsm4(ah[mt], uAH + aoff);
            ldsm4(al[mt], uAL + aoff);
        }
        uint32_t bkb = (uint32_t)ks*32 + bKadd;
        #pragma unroll
        for (int ntp = 0; ntp < 4; ++ntp){
            int rowB = ng*64 + ntp*16 + rowBl;
            uint32_t boff = (uint32_t)rowB*128u + (bkb ^ swx);
            uint32_t bh[4], bl[4];
            ldsm4(bh, uBH + boff);
            ldsm4(bl, uBL + boff);
            #pragma unroll
            for (int mt = 0; mt < 2; ++mt){
                mma_bf16(acc[mt][2*ntp],   ah[mt], bh[0], bh[1]);
                mma_bf16(acc[mt][2*ntp],   ah[mt], bl[0], bl[1]);
                mma_bf16(acc[mt][2*ntp],   al[mt], bh[0], bh[1]);
                mma_bf16(acc[mt][2*ntp+1], ah[mt], bh[2], bh[3]);
                mma_bf16(acc[mt][2*ntp+1], ah[mt], bl[2], bl[3]);
                mma_bf16(acc[mt][2*ntp+1], al[mt], bh[2], bh[3]);
            }
        }
    }
}

// =================== SIMT fp32 machinery (K1..K3 weight chain) ===========================
__device__ __forceinline__ void fma2(ull& d, ull a, ull b){
    asm("fma.rn.f32x2 %0, %1, %2, %0;" : "+l"(d) : "l"(a), "l"(b));
}
__device__ __forceinline__ ull pk2(float x, float y){
    ull r; asm("mov.b64 %0, {%1, %2};" : "=l"(r) : "f"(x), "f"(y)); return r;
}
__device__ __forceinline__ float2 upk(ull v){
    float2 f; asm("mov.b64 {%0, %1}, %2;" : "=f"(f.x), "=f"(f.y) : "l"(v)); return f;
}
struct F8 { float4 a, b; };
__device__ __forceinline__ F8 ldg_T(const float* __restrict__ src, int ld, int tid){
    int c4 = (tid & 3) * 4, r = tid >> 2;
    F8 f;
    f.a = *(const float4*)(src + (size_t)r*ld + c4);
    f.b = *(const float4*)(src + (size_t)(r+64)*ld + c4);
    return f;
}
__device__ __forceinline__ void sts_T(float (*dst)[LDT], F8 f, int tid){
    int c4 = (tid & 3) * 4, r = tid >> 2;
    dst[c4+0][r]    = f.a.x; dst[c4+1][r]    = f.a.y;
    dst[c4+2][r]    = f.a.z; dst[c4+3][r]    = f.a.w;
    dst[c4+0][r+64] = f.b.x; dst[c4+1][r+64] = f.b.y;
    dst[c4+2][r+64] = f.b.z; dst[c4+3][r+64] = f.b.w;
}
__device__ __forceinline__ F8 ldg_D(const float* __restrict__ src, int ld, int tid){
    int n4 = (tid & 15) * 4, k = tid >> 4;
    F8 f;
    f.a = *(const float4*)(src + (size_t)k*ld + n4);
    f.b = *(const float4*)(src + (size_t)k*ld + n4 + 64);
    return f;
}
__device__ __forceinline__ void sts_D(float (*dst)[LDT], F8 f, int tid){
    int n4 = (tid & 15) * 4, k = tid >> 4;
    *(float4*)(&dst[k][n4])      = f.a;
    *(float4*)(&dst[k][n4 + 64]) = f.b;
}
__device__ __forceinline__ void mm16(ull acc[8][4], const float (*As)[LDT],
                                     const float (*Bs)[LDT], int tx, int ty){
    #pragma unroll
    for (int k = 0; k < 16; ++k){
        float4 a0 = *(const float4*)(&As[k][ty*4]);
        float4 a1 = *(const float4*)(&As[k][64+ty*4]);
        float4 b0 = *(const float4*)(&Bs[k][tx*4]);
        float4 b1 = *(const float4*)(&Bs[k][64+tx*4]);
        ull bb0 = pk2(b0.x,b0.y), bb1 = pk2(b0.z,b0.w);
        ull bb2 = pk2(b1.x,b1.y), bb3 = pk2(b1.z,b1.w);
        float av[8] = {a0.x,a0.y,a0.z,a0.w,a1.x,a1.y,a1.z,a1.w};
        #pragma unroll
        for (int i = 0; i < 8; ++i){
            ull ad = pk2(av[i], av[i]);
            fma2(acc[i][0], ad, bb0);
            fma2(acc[i][1], ad, bb1);
            fma2(acc[i][2], ad, bb2);
            fma2(acc[i][3], ad, bb3);
        }
    }
}
__device__ __forceinline__ int row_of(int i, int ty){
    return (i < 4) ? (ty*4 + i) : (64 + ty*4 + (i-4));
}

// ================= K1..K3: flat [8192,256] x [256,256] GEMM chain (SIMT) =================
template<int STEP>
__global__ void __launch_bounds__(256, 2) sgemm_flat(const float* __restrict__ Ain,
                                                     const float* __restrict__ W){
    __shared__ __align__(16) float As[2][16][LDT], Bs[2][16][LDT];
    int tid = threadIdx.x, tx = tid & 15, ty = tid >> 4;
    const float* A = (STEP == 0) ? Ain : (STEP == 1 ? g_q : g_t2);
    float*       C = (STEP == 0) ? g_q : (STEP == 1 ? g_t2 : g_P);
    const float* Ab = A + (size_t)blockIdx.x * 128 * HH;
    int n0 = blockIdx.y * 128;
    const float* Bb = (STEP == 0) ? W + (size_t)n0*HH : W + n0;

    ull acc[8][4];
    #pragma unroll
    for (int i=0;i<8;i++){ acc[i][0]=acc[i][1]=acc[i][2]=acc[i][3]=0ULL; }

    F8 ra = ldg_T(Ab, HH, tid);
    F8 rb = (STEP == 0) ? ldg_T(Bb, HH, tid) : ldg_D(Bb, HH, tid);
    sts_T(As[0], ra, tid);
    if (STEP == 0) sts_T(Bs[0], rb, tid); else sts_D(Bs[0], rb, tid);
    __syncthreads();

    #pragma unroll 2
    for (int s = 0; s < 16; ++s){
        if (s < 15){
            ra = ldg_T(Ab + (s+1)*16, HH, tid);
            rb = (STEP == 0) ? ldg_T(Bb + (s+1)*16, HH, tid)
                             : ldg_D(Bb + (size_t)(s+1)*16*HH, HH, tid);
        }
        mm16(acc, As[s&1], Bs[s&1], tx, ty);
        if (s < 15){
            sts_T(As[(s+1)&1], ra, tid);
            if (STEP == 0) sts_T(Bs[(s+1)&1], rb, tid); else sts_D(Bs[(s+1)&1], rb, tid);
        }
        __syncthreads();
    }

    float* Cb = C + (size_t)blockIdx.x*128*HH + n0;
    #pragma unroll
    for (int i=0;i<8;i++){
        int row = row_of(i, ty);
        float2 p0=upk(acc[i][0]), p1=upk(acc[i][1]), p2=upk(acc[i][2]), p3=upk(acc[i][3]);
        *(float4*)(Cb + (size_t)row*HH + tx*4)      = make_float4(p0.x,p0.y,p1.x,p1.y);
        *(float4*)(Cb + (size_t)row*HH + 64 + tx*4) = make_float4(p2.x,p2.y,p3.x,p3.y);
    }
}

// ================= K4 (tensor): S = P_b @ X_p^T (+bias) -> softmax -> A ==================
// __launch_bounds__(256, 2): cap regs at 128 so two CTAs co-reside per SM (R12 post-mortem:
// 138 regs -> occ 12.4% -> regression despite lower LDS traffic).
__global__ void __launch_bounds__(256, 2) kernel_S_tc(const float* __restrict__ node,
                                                      const float* __restrict__ neigh,
                                                      const float* __restrict__ bias,
                                                      float* Aout){
    extern __shared__ char sm[];
    char* base = (char*)(((uintptr_t)sm + 1023) & ~(uintptr_t)1023);
    char* tPH = base;            char* tPL = base + 16384;
    char* tXH = base + 32768;    char* tXL = base + 49152;
    float* xchM = (float*)(base + 65536);        // [2][128]
    float* xchS = xchM + 256;                    // [2][128]
    uint32_t uPH = smem_u32(tPH), uPL = smem_u32(tPL);
    uint32_t uXH = smem_u32(tXH), uXL = smem_u32(tXL);

    int tid = threadIdx.x, w = tid >> 5, l = tid & 31;
    int mg = w >> 1, ng = w & 1;
    int p = blockIdx.x, b = p / NP1;
    const float* P = g_P + (size_t)b*TT*HH;
    const float* X = pair_base(p, node, neigh);
    float* Ao = Aout ? Aout : g_Afb;

    float acc[2][8][4];
    #pragma unroll
    for (int i=0;i<2;i++)
        #pragma unroll
        for (int j=0;j<8;j++){ acc[i][j][0]=acc[i][j][1]=acc[i][j][2]=acc[i][j][3]=0.f; }

    for (int s = 0; s < 4; ++s){
        cvt_tile(tPH, tPL, P + s*64, HH, tid);
        cvt_tile(tXH, tXL, X + s*64, HH, tid);
        __syncthreads();
        slab_mma_warp(acc, uPH, uPL, uXH, uXL, mg, ng, l);
        __syncthreads();
    }

    // epilogue: lane owns rows r(mt,hf) = 32mg + 16mt + 8hf + (l>>2),
    // cols 64ng + nt*8 + q*2 (+1). Softmax over full 128 cols -> combine ng pair via smem.
    int q = l & 3, rb = l >> 2;

    #pragma unroll
    for (int nt = 0; nt < 8; ++nt){
        float2 bb = *(const float2*)(bias + ng*64 + nt*8 + q*2);
        #pragma unroll
        for (int mt = 0; mt < 2; ++mt){
            acc[mt][nt][0] += bb.x; acc[mt][nt][1] += bb.y;
            acc[mt][nt][2] += bb.x; acc[mt][nt][3] += bb.y;
        }
    }
    float mx[2][2];
    #pragma unroll
    for (int mt = 0; mt < 2; ++mt){
        mx[mt][0] = -1e30f; mx[mt][1] = -1e30f;
        #pragma unroll
        for (int nt = 0; nt < 8; ++nt){
            mx[mt][0] = fmaxf(mx[mt][0], fmaxf(acc[mt][nt][0], acc[mt][nt][1]));
            mx[mt][1] = fmaxf(mx[mt][1], fmaxf(acc[mt][nt][2], acc[mt][nt][3]));
        }
        #pragma unroll
        for (int o = 1; o <= 2; o <<= 1){
            mx[mt][0] = fmaxf(mx[mt][0], __shfl_xor_sync(0xffffffffu, mx[mt][0], o));
            mx[mt][1] = fmaxf(mx[mt][1], __shfl_xor_sync(0xffffffffu, mx[mt][1], o));
        }
    }
    if (q == 0){
        #pragma unroll
        for (int mt = 0; mt < 2; ++mt){
            xchM[ng*128 + 32*mg + 16*mt + rb]     = mx[mt][0];
            xchM[ng*128 + 32*mg + 16*mt + 8 + rb] = mx[mt][1];
        }
    }
    __syncthreads();
    float sum[2][2];
    #pragma unroll
    for (int mt = 0; mt < 2; ++mt){
        int r0 = 32*mg + 16*mt + rb;
        float m0 = fmaxf(xchM[r0],     xchM[128 + r0]);
        float m1 = fmaxf(xchM[r0 + 8], xchM[128 + r0 + 8]);
        sum[mt][0] = 0.f; sum[mt][1] = 0.f;
        #pragma unroll
        for (int nt = 0; nt < 8; ++nt){
            acc[mt][nt][0] = __expf(acc[mt][nt][0] - m0); sum[mt][0] += acc[mt][nt][0];
            acc[mt][nt][1] = __expf(acc[mt][nt][1] - m0); sum[mt][0] += acc[mt][nt][1];
            acc[mt][nt][2] = __expf(acc[mt][nt][2] - m1); sum[mt][1] += acc[mt][nt][2];
            acc[mt][nt][3] = __expf(acc[mt][nt][3] - m1); sum[mt][1] += acc[mt][nt][3];
        }
        #pragma unroll
        for (int o = 1; o <= 2; o <<= 1){
            sum[mt][0] += __shfl_xor_sync(0xffffffffu, sum[mt][0], o);
            sum[mt][1] += __shfl_xor_sync(0xffffffffu, sum[mt][1], o);
        }
    }
    if (q == 0){
        #pragma unroll
        for (int mt = 0; mt < 2; ++mt){
            xchS[ng*128 + 32*mg + 16*mt + rb]     = sum[mt][0];
            xchS[ng*128 + 32*mg + 16*mt + 8 + rb] = sum[mt][1];
        }
    }
    __syncthreads();
    float* Ap = Ao + (size_t)p*TT*TT;
    #pragma unroll
    for (int mt = 0; mt < 2; ++mt){
        int r0 = 32*mg + 16*mt + rb, r1 = r0 + 8;
        float i0 = 1.f / (xchS[r0] + xchS[128 + r0]);
        float i1 = 1.f / (xchS[r1] + xchS[128 + r1]);
        #pragma unroll
        for (int nt = 0; nt < 8; ++nt){
            *(float2*)(Ap + (size_t)r0*TT + ng*64 + nt*8 + q*2) =
                make_float2(acc[mt][nt][0]*i0, acc[mt][nt][1]*i0);
            *(float2*)(Ap + (size_t)r1*TT + ng*64 + nt*8 + q*2) =
                make_float2(acc[mt][nt][2]*i1, acc[mt][nt][3]*i1);
        }
    }
}

// ================= K5 (tensor): Vt[c,s] = Wv_chunk @ X^T ; O = A @ Vt^T ==================
__global__ void __launch_bounds__(256, 2) kernel_VO_tc(const float* __restrict__ node,
                                                       const float* __restrict__ neigh,
                                                       const float* __restrict__ Wv,
                                                       const float* Ain,
                                                       float* __restrict__ Out){
    extern __shared__ char sm[];
    char* base = (char*)(((uintptr_t)sm + 1023) & ~(uintptr_t)1023);
    char* T0 = base;          char* T1 = base + 16384;
    char* T2 = base + 32768;  char* T3 = base + 49152;
    char* T4 = base + 65536;  char* T5 = base + 81920;
    uint32_t u0 = smem_u32(T0), u1 = smem_u32(T1), u2 = smem_u32(T2);
    uint32_t u3 = smem_u32(T3), u4 = smem_u32(T4), u5 = smem_u32(T5);

    int tid = threadIdx.x, w = tid >> 5, l = tid & 31;
    int mg = w >> 1, ng = w & 1;
    int p = blockIdx.x;
    int n0 = blockIdx.y * 128;
    const float* X  = pair_base(p, node, neigh);
    const float* Wc = Wv + (size_t)n0*HH;
    const float* Ap = (Ain ? Ain : (const float*)g_Afb) + (size_t)p*TT*TT;

    float acc[2][8][4];
    #pragma unroll
    for (int i=0;i<2;i++)
        #pragma unroll
        for (int j=0;j<8;j++){ acc[i][j][0]=acc[i][j][1]=acc[i][j][2]=acc[i][j][3]=0.f; }

    // ---- Phase 1: D1[c, s] = sum_h Wv[n0+c, h] * X[s, h] ----
    for (int s = 0; s < 4; ++s){
        cvt_tile(T0, T1, Wc + s*64, HH, tid);
        cvt_tile(T2, T3, X  + s*64, HH, tid);
        __syncthreads();
        slab_mma_warp(acc, u0, u1, u2, u3, mg, ng, l);
        __syncthreads();
    }

    // ---- Phase 2: split-convert D1 into persistent Vt tiles ----
    // Vt[c][s_local]: s-half 0 (ng==0) -> hi T0 / lo T1 ; s-half 1 (ng==1) -> T2 / T3
    {
        int q = l & 3, rb = l >> 2;
        char* th = ng ? T2 : T0;
        char* tl = ng ? T3 : T1;
        #pragma unroll
        for (int mt = 0; mt < 2; ++mt){
            #pragma unroll
            for (int hf = 0; hf < 2; ++hf){
                int c = 32*mg + 16*mt + 8*hf + rb;
                uint32_t swc = (uint32_t)(c & 7) << 4;
                #pragma unroll
                for (int nt = 0; nt < 8; ++nt){
                    int sl = nt*8 + q*2;
                    float a = acc[mt][nt][2*hf], bq = acc[mt][nt][2*hf+1];
                    uint32_t hi = pack_bf(a, bq);
                    float la = a  - __uint_as_float(hi << 16);
                    float lb = bq - __uint_as_float(hi & 0xffff0000u);
                    uint32_t lo = pack_bf(la, lb);
                    uint32_t boff = (uint32_t)c*128u + (uint32_t)sl*2u;
                    uint32_t swz = boff ^ swc;
                    *(uint32_t*)(th + swz) = hi;
                    *(uint32_t*)(tl + swz) = lo;
                }
            }
        }
        #pragma unroll
        for (int i=0;i<2;i++)
            #pragma unroll
            for (int j=0;j<8;j++){ acc[i][j][0]=acc[i][j][1]=acc[i][j][2]=acc[i][j][3]=0.f; }
    }
    __syncthreads();

    // ---- Phase 3: D2[t, c] = sum_s A[t, s] * Vt[c, s] ----
    for (int s2 = 0; s2 < 2; ++s2){
        cvt_tile(T4, T5, Ap + s2*64, TT, tid);
        __syncthreads();
        slab_mma_warp(acc, u4, u5, s2 ? u2 : u0, s2 ? u3 : u1, mg, ng, l);
        __syncthreads();
    }

    // ---- Phase 4: store O[t, n0 + c] ----
    {
        int q = l & 3, rb = l >> 2;
        float* Ob = Out + (size_t)p*TT*HH + n0;
        #pragma unroll
        for (int mt = 0; mt < 2; ++mt){
            int t0 = 32*mg + 16*mt + rb, t1 = t0 + 8;
            #pragma unroll
            for (int nt = 0; nt < 8; ++nt){
                *(float2*)(Ob + (size_t)t0*HH + ng*64 + nt*8 + q*2) =
                    make_float2(acc[mt][nt][0], acc[mt][nt][1]);
                *(float2*)(Ob + (size_t)t1*HH + ng*64 + nt*8 + q*2) =
                    make_float2(acc[mt][nt][2], acc[mt][nt][3]);
            }
        }
    }
}

// =========================================================================================
extern "C" void kernel_launch(void* const* d_in, const int* in_sizes, int n_in,
                              void* d_out, int out_size){
    const float* node  = (const float*)d_in[0];
    const float* neigh = (const float*)d_in[1];
    int w = (n_in >= 8) ? 2 : 1;
    const float* Wq = (const float*)d_in[w+1];
    const float* Wk = (const float*)d_in[w+2];
    const float* Wv = (const float*)d_in[w+3];
    const float* Wb = (const float*)d_in[w+4];
    const float* bv = (const float*)d_in[w+5];

    float* out = (float*)d_out;
    const long long O_ELEMS = (long long)NPAIRS*TT*HH;
    const long long A_ELEMS = (long long)NPAIRS*TT*TT;
    float* Aout = ((long long)out_size >= O_ELEMS + A_ELEMS) ? (out + O_ELEMS) : nullptr;

    const int S_SMEM  = 4*16384 + 2048 + 1024;   // 4 bf16 tiles + softmax xchg + align pad
    const int VO_SMEM = 6*16384 + 1024;          // 6 bf16 tiles + align pad
    cudaFuncSetAttribute(kernel_S_tc,  cudaFuncAttributeMaxDynamicSharedMemorySize, S_SMEM);
    cudaFuncSetAttribute(kernel_VO_tc, cudaFuncAttributeMaxDynamicSharedMemorySize, VO_SMEM);

    dim3 thr(256);
    sgemm_flat<0><<<dim3(64,2), thr>>>(node, Wq);        // g_q  = node @ Wq^T
    sgemm_flat<1><<<dim3(64,2), thr>>>(nullptr, Wb);     // g_t2 = g_q @ Wb
    sgemm_flat<2><<<dim3(64,2), thr>>>(nullptr, Wk);     // g_P  = g_t2 @ Wk
    kernel_S_tc <<<dim3(NPAIRS,1), thr, S_SMEM>>>(node, neigh, bv, Aout);
    kernel_VO_tc<<<dim3(NPAIRS,2), thr, VO_SMEM>>>(node, neigh, Wv, Aout, out);
}

// round 14
// speedup vs baseline: 1.1869x; 1.0231x over previous
#include <cuda_runtime.h>
#include <cstdint>

typedef unsigned long long ull;

#define BB 64
#define NN 16
#define TT 128
#define HH 256
#define NP1 17
#define NPAIRS (BB*NP1)   // 1088
#define LDT 132           // padded smem row stride for SIMT kernels
#define TPAD 80           // bytes/row of a [128 x 32] bf16 tile; 16B*5 (odd stride) -> conflict-free ldmatrix
#define TILE32 (128*TPAD) // 10240 B

// ---------------- scratch (static device globals; no runtime allocation) ----------------
__device__ float g_q  [BB*TT*HH];
__device__ float g_t2 [BB*TT*HH];
__device__ float g_P  [BB*TT*HH];
__device__ float g_Afb[(size_t)NPAIRS*TT*TT];

// =================== PTX helpers =========================================================
__device__ __forceinline__ uint32_t smem_u32(const void* p){
    uint32_t a;
    asm("{ .reg .u64 t; cvta.to.shared.u64 t, %1; cvt.u32.u64 %0, t; }" : "=r"(a) : "l"(p));
    return a;
}
// pack_bf(a,b): 32-bit word, low16 = bf16(a), high16 = bf16(b)
__device__ __forceinline__ uint32_t pack_bf(float a, float b){
    uint32_t r;
    asm("cvt.rn.satfinite.bf16x2.f32 %0, %1, %2;" : "=r"(r) : "f"(b), "f"(a));
    return r;
}
__device__ __forceinline__ void ldsm4(uint32_t r[4], uint32_t addr){
    asm volatile("ldmatrix.sync.aligned.m8n8.x4.shared.b16 {%0,%1,%2,%3}, [%4];"
        : "=r"(r[0]), "=r"(r[1]), "=r"(r[2]), "=r"(r[3]) : "r"(addr));
}
__device__ __forceinline__ void mma_bf16(float c[4], const uint32_t a[4],
                                         uint32_t b0, uint32_t b1){
    asm volatile(
        "mma.sync.aligned.m16n8k16.row.col.f32.bf16.bf16.f32 "
        "{%0,%1,%2,%3}, {%4,%5,%6,%7}, {%8,%9}, {%0,%1,%2,%3};"
        : "+f"(c[0]), "+f"(c[1]), "+f"(c[2]), "+f"(c[3])
        : "r"(a[0]), "r"(a[1]), "r"(a[2]), "r"(a[3]), "r"(b0), "r"(b1));
}

__device__ __forceinline__ const float* pair_base(int p, const float* node, const float* neigh){
    int b = p / NP1, n = p % NP1;
    return (n == 0) ? node  + (size_t)b*TT*HH
                    : neigh + (size_t)(b*NN + (n-1))*TT*HH;
}

// ---------------- pipelined staging: LDG fp32 [128x32] slab -> regs -> split bf16 tiles --
__device__ __forceinline__ void ldg_slab32(float4 f[4], const float* __restrict__ src,
                                           int ld, int tid){
    int row = tid >> 1, c0 = (tid & 1) * 16;
    const float* s = src + (size_t)row*ld + c0;
    f[0] = *(const float4*)(s);
    f[1] = *(const float4*)(s + 4);
    f[2] = *(const float4*)(s + 8);
    f[3] = *(const float4*)(s + 12);
}
__device__ __forceinline__ void cvt_sts32(char* th, char* tl, const float4 f[4], int tid){
    int row = tid >> 1, c0 = (tid & 1) * 16;
    char* dh = th + row*TPAD + c0*2;
    char* dl = tl + row*TPAD + c0*2;
    #pragma unroll
    for (int j = 0; j < 4; ++j){
        float4 v = f[j];
        uint32_t h0 = pack_bf(v.x, v.y), h1 = pack_bf(v.z, v.w);
        float lx = v.x - __uint_as_float(h0 << 16);
        float ly = v.y - __uint_as_float(h0 & 0xffff0000u);
        float lz = v.z - __uint_as_float(h1 << 16);
        float lw = v.w - __uint_as_float(h1 & 0xffff0000u);
        uint32_t l0 = pack_bf(lx, ly), l1 = pack_bf(lz, lw);
        *(ull*)(dh + 8*j) = (ull)h0 | ((ull)h1 << 32);
        *(ull*)(dl + 8*j) = (ull)l0 | ((ull)l1 << 32);
    }
}

// ---------------- one K=32 slab of split MMAs, 2D warp tiling (80B-pad tiles) ------------
// warp (mg, ng): rows [32*mg, +32) as 2 m-tiles, cols [64*ng, +64) as 8 n-tiles.
__device__ __forceinline__ void slab_mma32(float acc[2][8][4],
                                           uint32_t uAH, uint32_t uAL,
                                           uint32_t uBH, uint32_t uBL,
                                           int mg, int ng, int l){
    int r8 = l & 7;
    uint32_t aKadd = ((l>>4)&1) * 16;
    int rowA0 = 32*mg + ((l>>3)&1)*8 + r8;
    int rowBl = ((l>>4)&1)*8 + r8;
    uint32_t bKadd = ((l>>3)&1) * 16;
    #pragma unroll
    for (int ks = 0; ks < 2; ++ks){
        uint32_t ah[2][4], al[2][4];
        #pragma unroll
        for (int mt = 0; mt < 2; ++mt){
            uint32_t aoff = (uint32_t)(rowA0 + 16*mt)*TPAD + (uint32_t)ks*32 + aKadd;
            ldsm4(ah[mt], uAH + aoff);
            ldsm4(al[mt], uAL + aoff);
        }
        #pragma unroll
        for (int ntp = 0; ntp < 4; ++ntp){
            uint32_t boff = (uint32_t)(ng*64 + ntp*16 + rowBl)*TPAD + (uint32_t)ks*32 + bKadd;
            uint32_t bh[4], bl[4];
            ldsm4(bh, uBH + boff);
            ldsm4(bl, uBL + boff);
            #pragma unroll
            for (int mt = 0; mt < 2; ++mt){
                mma_bf16(acc[mt][2*ntp],   ah[mt], bh[0], bh[1]);
                mma_bf16(acc[mt][2*ntp],   ah[mt], bl[0], bl[1]);
                mma_bf16(acc[mt][2*ntp],   al[mt], bh[0], bh[1]);
                mma_bf16(acc[mt][2*ntp+1], ah[mt], bh[2], bh[3]);
                mma_bf16(acc[mt][2*ntp+1], ah[mt], bl[2], bl[3]);
                mma_bf16(acc[mt][2*ntp+1], al[mt], bh[2], bh[3]);
            }
        }
    }
}

// same, but B operand in the OLD format: 128B rows, 64 k-cols, XOR (row&7)<<4 swizzle.
// srem2 = byte offset of this slab's k-base within the tile ((s_base % 64) * 2).
__device__ __forceinline__ void slab_mma32_bold(float acc[2][8][4],
                                                uint32_t uAH, uint32_t uAL,
                                                uint32_t uBH, uint32_t uBL, uint32_t srem2,
                                                int mg, int ng, int l){
    int r8 = l & 7;
    uint32_t aKadd = ((l>>4)&1) * 16;
    int rowA0 = 32*mg + ((l>>3)&1)*8 + r8;
    int rowBl = ((l>>4)&1)*8 + r8;
    uint32_t bKadd = ((l>>3)&1) * 16;
    #pragma unroll
    for (int ks = 0; ks < 2; ++ks){
        uint32_t ah[2][4], al[2][4];
        #pragma unroll
        for (int mt = 0; mt < 2; ++mt){
            uint32_t aoff = (uint32_t)(rowA0 + 16*mt)*TPAD + (uint32_t)ks*32 + aKadd;
            ldsm4(ah[mt], uAH + aoff);
            ldsm4(al[mt], uAL + aoff);
        }
        uint32_t kb = srem2 + (uint32_t)ks*32 + bKadd;
        #pragma unroll
        for (int ntp = 0; ntp < 4; ++ntp){
            int rowB = ng*64 + ntp*16 + rowBl;
            uint32_t boff = (uint32_t)rowB*128u + (kb ^ ((uint32_t)(rowB & 7) << 4));
            uint32_t bh[4], bl[4];
            ldsm4(bh, uBH + boff);
            ldsm4(bl, uBL + boff);
            #pragma unroll
            for (int mt = 0; mt < 2; ++mt){
                mma_bf16(acc[mt][2*ntp],   ah[mt], bh[0], bh[1]);
                mma_bf16(acc[mt][2*ntp],   ah[mt], bl[0], bl[1]);
                mma_bf16(acc[mt][2*ntp],   al[mt], bh[0], bh[1]);
                mma_bf16(acc[mt][2*ntp+1], ah[mt], bh[2], bh[3]);
                mma_bf16(acc[mt][2*ntp+1], ah[mt], bl[2], bl[3]);
                mma_bf16(acc[mt][2*ntp+1], al[mt], bh[2], bh[3]);
            }
        }
    }
}

// =================== SIMT fp32 machinery (K1..K3 weight chain, unchanged) ================
__device__ __forceinline__ void fma2(ull& d, ull a, ull b){
    asm("fma.rn.f32x2 %0, %1, %2, %0;" : "+l"(d) : "l"(a), "l"(b));
}
__device__ __forceinline__ ull pk2(float x, float y){
    ull r; asm("mov.b64 %0, {%1, %2};" : "=l"(r) : "f"(x), "f"(y)); return r;
}
__device__ __forceinline__ float2 upk(ull v){
    float2 f; asm("mov.b64 {%0, %1}, %2;" : "=f"(f.x), "=f"(f.y) : "l"(v)); return f;
}
struct F8 { float4 a, b; };
__device__ __forceinline__ F8 ldg_T(const float* __restrict__ src, int ld, int tid){
    int c4 = (tid & 3) * 4, r = tid >> 2;
    F8 f;
    f.a = *(const float4*)(src + (size_t)r*ld + c4);
    f.b = *(const float4*)(src + (size_t)(r+64)*ld + c4);
    return f;
}
__device__ __forceinline__ void sts_T(float (*dst)[LDT], F8 f, int tid){
    int c4 = (tid & 3) * 4, r = tid >> 2;
    dst[c4+0][r]    = f.a.x; dst[c4+1][r]    = f.a.y;
    dst[c4+2][r]    = f.a.z; dst[c4+3][r]    = f.a.w;
    dst[c4+0][r+64] = f.b.x; dst[c4+1][r+64] = f.b.y;
    dst[c4+2][r+64] = f.b.z; dst[c4+3][r+64] = f.b.w;
}
__device__ __forceinline__ F8 ldg_D(const float* __restrict__ src, int ld, int tid){
    int n4 = (tid & 15) * 4, k = tid >> 4;
    F8 f;
    f.a = *(const float4*)(src + (size_t)k*ld + n4);
    f.b = *(const float4*)(src + (size_t)k*ld + n4 + 64);
    return f;
}
__device__ __forceinline__ void sts_D(float (*dst)[LDT], F8 f, int tid){
    int n4 = (tid & 15) * 4, k = tid >> 4;
    *(float4*)(&dst[k][n4])      = f.a;
    *(float4*)(&dst[k][n4 + 64]) = f.b;
}
__device__ __forceinline__ void mm16(ull acc[8][4], const float (*As)[LDT],
                                     const float (*Bs)[LDT], int tx, int ty){
    #pragma unroll
    for (int k = 0; k < 16; ++k){
        float4 a0 = *(const float4*)(&As[k][ty*4]);
        float4 a1 = *(const float4*)(&As[k][64+ty*4]);
        float4 b0 = *(const float4*)(&Bs[k][tx*4]);
        float4 b1 = *(const float4*)(&Bs[k][64+tx*4]);
        ull bb0 = pk2(b0.x,b0.y), bb1 = pk2(b0.z,b0.w);
        ull bb2 = pk2(b1.x,b1.y), bb3 = pk2(b1.z,b1.w);
        float av[8] = {a0.x,a0.y,a0.z,a0.w,a1.x,a1.y,a1.z,a1.w};
        #pragma unroll
        for (int i = 0; i < 8; ++i){
            ull ad = pk2(av[i], av[i]);
            fma2(acc[i][0], ad, bb0);
            fma2(acc[i][1], ad, bb1);
            fma2(acc[i][2], ad, bb2);
            fma2(acc[i][3], ad, bb3);
        }
    }
}
__device__ __forceinline__ int row_of(int i, int ty){
    return (i < 4) ? (ty*4 + i) : (64 + ty*4 + (i-4));
}

// ================= K1..K3: flat [8192,256] x [256,256] GEMM chain (SIMT) =================
template<int STEP>
__global__ void __launch_bounds__(256, 2) sgemm_flat(const float* __restrict__ Ain,
                                                     const float* __restrict__ W){
    __shared__ __align__(16) float As[2][16][LDT], Bs[2][16][LDT];
    int tid = threadIdx.x, tx = tid & 15, ty = tid >> 4;
    const float* A = (STEP == 0) ? Ain : (STEP == 1 ? g_q : g_t2);
    float*       C = (STEP == 0) ? g_q : (STEP == 1 ? g_t2 : g_P);
    const float* Ab = A + (size_t)blockIdx.x * 128 * HH;
    int n0 = blockIdx.y * 128;
    const float* Bb = (STEP == 0) ? W + (size_t)n0*HH : W + n0;

    ull acc[8][4];
    #pragma unroll
    for (int i=0;i<8;i++){ acc[i][0]=acc[i][1]=acc[i][2]=acc[i][3]=0ULL; }

    F8 ra = ldg_T(Ab, HH, tid);
    F8 rb = (STEP == 0) ? ldg_T(Bb, HH, tid) : ldg_D(Bb, HH, tid);
    sts_T(As[0], ra, tid);
    if (STEP == 0) sts_T(Bs[0], rb, tid); else sts_D(Bs[0], rb, tid);
    __syncthreads();

    #pragma unroll 2
    for (int s = 0; s < 16; ++s){
        if (s < 15){
            ra = ldg_T(Ab + (s+1)*16, HH, tid);
            rb = (STEP == 0) ? ldg_T(Bb + (s+1)*16, HH, tid)
                             : ldg_D(Bb + (size_t)(s+1)*16*HH, HH, tid);
        }
        mm16(acc, As[s&1], Bs[s&1], tx, ty);
        if (s < 15){
            sts_T(As[(s+1)&1], ra, tid);
            if (STEP == 0) sts_T(Bs[(s+1)&1], rb, tid); else sts_D(Bs[(s+1)&1], rb, tid);
        }
        __syncthreads();
    }

    float* Cb = C + (size_t)blockIdx.x*128*HH + n0;
    #pragma unroll
    for (int i=0;i<8;i++){
        int row = row_of(i, ty);
        float2 p0=upk(acc[i][0]), p1=upk(acc[i][1]), p2=upk(acc[i][2]), p3=upk(acc[i][3]);
        *(float4*)(Cb + (size_t)row*HH + tx*4)      = make_float4(p0.x,p0.y,p1.x,p1.y);
        *(float4*)(Cb + (size_t)row*HH + 64 + tx*4) = make_float4(p2.x,p2.y,p3.x,p3.y);
    }
}

// ================= K4 (tensor): S = P_b @ X_p^T (+bias) -> softmax -> A ==================
// Pipelined K=32 slabs: mma(buf s) || cvt(s+1 from regs) -> LDG(s+2) -> one sync per slab.
__global__ void __launch_bounds__(256, 2) kernel_S_tc(const float* __restrict__ node,
                                                      const float* __restrict__ neigh,
                                                      const float* __restrict__ bias,
                                                      float* Aout){
    extern __shared__ char sm[];
    char* base = (char*)(((uintptr_t)sm + 1023) & ~(uintptr_t)1023);
    // buf b: [PH][PL][XH][XL] each TILE32
    float* xchM = (float*)(base + 8*TILE32);     // [2][128]
    float* xchS = xchM + 256;                    // [2][128]

    int tid = threadIdx.x, w = tid >> 5, l = tid & 31;
    int mg = w >> 1, ng = w & 1;
    int p = blockIdx.x, b = p / NP1;
    const float* P = g_P + (size_t)b*TT*HH;
    const float* X = pair_base(p, node, neigh);
    float* Ao = Aout ? Aout : g_Afb;

    float acc[2][8][4];
    #pragma unroll
    for (int i=0;i<2;i++)
        #pragma unroll
        for (int j=0;j<8;j++){ acc[i][j][0]=acc[i][j][1]=acc[i][j][2]=acc[i][j][3]=0.f; }

    float4 fP[4], fX[4];
    ldg_slab32(fP, P, HH, tid);
    ldg_slab32(fX, X, HH, tid);
    cvt_sts32(base + 0*TILE32, base + 1*TILE32, fP, tid);
    cvt_sts32(base + 2*TILE32, base + 3*TILE32, fX, tid);
    ldg_slab32(fP, P + 32, HH, tid);
    ldg_slab32(fX, X + 32, HH, tid);
    __syncthreads();

    #pragma unroll 2
    for (int s = 0; s < 8; ++s){
        char* cur = base + (size_t)(s&1)*4*TILE32;
        slab_mma32(acc, smem_u32(cur), smem_u32(cur + TILE32),
                        smem_u32(cur + 2*TILE32), smem_u32(cur + 3*TILE32), mg, ng, l);
        if (s < 7){
            char* nxt = base + (size_t)((s+1)&1)*4*TILE32;
            cvt_sts32(nxt + 0*TILE32, nxt + 1*TILE32, fP, tid);
            cvt_sts32(nxt + 2*TILE32, nxt + 3*TILE32, fX, tid);
        }
        if (s < 6){
            ldg_slab32(fP, P + (s+2)*32, HH, tid);
            ldg_slab32(fX, X + (s+2)*32, HH, tid);
        }
        __syncthreads();
    }

    // epilogue (unchanged from R13): bias + softmax over 128 cols, ng-pair combine via smem
    int q = l & 3, rb = l >> 2;
    #pragma unroll
    for (int nt = 0; nt < 8; ++nt){
        float2 bb = *(const float2*)(bias + ng*64 + nt*8 + q*2);
        #pragma unroll
        for (int mt = 0; mt < 2; ++mt){
            acc[mt][nt][0] += bb.x; acc[mt][nt][1] += bb.y;
            acc[mt][nt][2] += bb.x; acc[mt][nt][3] += bb.y;
        }
    }
    float mx[2][2];
    #pragma unroll
    for (int mt = 0; mt < 2; ++mt){
        mx[mt][0] = -1e30f; mx[mt][1] = -1e30f;
        #pragma unroll
        for (int nt = 0; nt < 8; ++nt){
            mx[mt][0] = fmaxf(mx[mt][0], fmaxf(acc[mt][nt][0], acc[mt][nt][1]));
            mx[mt][1] = fmaxf(mx[mt][1], fmaxf(acc[mt][nt][2], acc[mt][nt][3]));
        }
        #pragma unroll
        for (int o = 1; o <= 2; o <<= 1){
            mx[mt][0] = fmaxf(mx[mt][0], __shfl_xor_sync(0xffffffffu, mx[mt][0], o));
            mx[mt][1] = fmaxf(mx[mt][1], __shfl_xor_sync(0xffffffffu, mx[mt][1], o));
        }
    }
    if (q == 0){
        #pragma unroll
        for (int mt = 0; mt < 2; ++mt){
            xchM[ng*128 + 32*mg + 16*mt + rb]     = mx[mt][0];
            xchM[ng*128 + 32*mg + 16*mt + 8 + rb] = mx[mt][1];
        }
    }
    __syncthreads();
    float sum[2][2];
    #pragma unroll
    for (int mt = 0; mt < 2; ++mt){
        int r0 = 32*mg + 16*mt + rb;
        float m0 = fmaxf(xchM[r0],     xchM[128 + r0]);
        float m1 = fmaxf(xchM[r0 + 8], xchM[128 + r0 + 8]);
        sum[mt][0] = 0.f; sum[mt][1] = 0.f;
        #pragma unroll
        for (int nt = 0; nt < 8; ++nt){
            acc[mt][nt][0] = __expf(acc[mt][nt][0] - m0); sum[mt][0] += acc[mt][nt][0];
            acc[mt][nt][1] = __expf(acc[mt][nt][1] - m0); sum[mt][0] += acc[mt][nt][1];
            acc[mt][nt][2] = __expf(acc[mt][nt][2] - m1); sum[mt][1] += acc[mt][nt][2];
            acc[mt][nt][3] = __expf(acc[mt][nt][3] - m1); sum[mt][1] += acc[mt][nt][3];
        }
        #pragma unroll
        for (int o = 1; o <= 2; o <<= 1){
            sum[mt][0] += __shfl_xor_sync(0xffffffffu, sum[mt][0], o);
            sum[mt][1] += __shfl_xor_sync(0xffffffffu, sum[mt][1], o);
        }
    }
    if (q == 0){
        #pragma unroll
        for (int mt = 0; mt < 2; ++mt){
            xchS[ng*128 + 32*mg + 16*mt + rb]     = sum[mt][0];
            xchS[ng*128 + 32*mg + 16*mt + 8 + rb] = sum[mt][1];
        }
    }
    __syncthreads();
    float* Ap = Ao + (size_t)p*TT*TT;
    #pragma unroll
    for (int mt = 0; mt < 2; ++mt){
        int r0 = 32*mg + 16*mt + rb, r1 = r0 + 8;
        float i0 = 1.f / (xchS[r0] + xchS[128 + r0]);
        float i1 = 1.f / (xchS[r1] + xchS[128 + r1]);
        #pragma unroll
        for (int nt = 0; nt < 8; ++nt){
            *(float2*)(Ap + (size_t)r0*TT + ng*64 + nt*8 + q*2) =
                make_float2(acc[mt][nt][0]*i0, acc[mt][nt][1]*i0);
            *(float2*)(Ap + (size_t)r1*TT + ng*64 + nt*8 + q*2) =
                make_float2(acc[mt][nt][2]*i1, acc[mt][nt][3]*i1);
        }
    }
}

// ================= K5 (tensor): Vt[c,s] = Wv_chunk @ X^T ; O = A @ Vt^T ==================
// Phase1/3 pipelined K=32 slabs; Vt kept in the proven old 128B/XOR format (written in
// phase2, read as B in phase3 via slab_mma32_bold).
__global__ void __launch_bounds__(256, 2) kernel_VO_tc(const float* __restrict__ node,
                                                       const float* __restrict__ neigh,
                                                       const float* __restrict__ Wv,
                                                       const float* Ain,
                                                       float* __restrict__ Out){
    extern __shared__ char sm[];
    char* base = (char*)(((uintptr_t)sm + 1023) & ~(uintptr_t)1023);
    // phase1 staging: buf b at base + b*4*TILE32 : [WH][WL][XH][XL]   (81920 B)
    // phase2 Vt (overwrites staging): VtH0 @0, VtL0 @16384, VtH1 @32768, VtL1 @49152
    // phase3 A staging: buf b at base + 65536 + b*2*TILE32 : [AH][AL] (40960 B)
    char* VtH0 = base;          char* VtL0 = base + 16384;
    char* VtH1 = base + 32768;  char* VtL1 = base + 49152;

    int tid = threadIdx.x, w = tid >> 5, l = tid & 31;
    int mg = w >> 1, ng = w & 1;
    int p = blockIdx.x;
    int n0 = blockIdx.y * 128;
    const float* X  = pair_base(p, node, neigh);
    const float* Wc = Wv + (size_t)n0*HH;
    const float* Ap = (Ain ? Ain : (const float*)g_Afb) + (size_t)p*TT*TT;

    float acc[2][8][4];
    #pragma unroll
    for (int i=0;i<2;i++)
        #pragma unroll
        for (int j=0;j<8;j++){ acc[i][j][0]=acc[i][j][1]=acc[i][j][2]=acc[i][j][3]=0.f; }

    // ---- Phase 1: D1[c, s] = sum_h Wv[n0+c, h] * X[s, h]  (8 pipelined slabs) ----
    {
        float4 fW[4], fX[4];
        ldg_slab32(fW, Wc, HH, tid);
        ldg_slab32(fX, X,  HH, tid);
        cvt_sts32(base + 0*TILE32, base + 1*TILE32, fW, tid);
        cvt_sts32(base + 2*TILE32, base + 3*TILE32, fX, tid);
        ldg_slab32(fW, Wc + 32, HH, tid);
        ldg_slab32(fX, X  + 32, HH, tid);
        __syncthreads();

        #pragma unroll 2
        for (int s = 0; s < 8; ++s){
            char* cur = base + (size_t)(s&1)*4*TILE32;
            slab_mma32(acc, smem_u32(cur), smem_u32(cur + TILE32),
                            smem_u32(cur + 2*TILE32), smem_u32(cur + 3*TILE32), mg, ng, l);
            if (s < 7){
                char* nxt = base + (size_t)((s+1)&1)*4*TILE32;
                cvt_sts32(nxt + 0*TILE32, nxt + 1*TILE32, fW, tid);
                cvt_sts32(nxt + 2*TILE32, nxt + 3*TILE32, fX, tid);
            }
            if (s < 6){
                ldg_slab32(fW, Wc + (s+2)*32, HH, tid);
                ldg_slab32(fX, X  + (s+2)*32, HH, tid);
            }
            __syncthreads();
        }
    }

    // ---- Phase 2: split-convert D1 (regs) into Vt tiles (old 128B/XOR format) ----
    // plus: prefetch + stage phase-3 A slab 0 before the single sync.
    {
        float4 fA[4];
        ldg_slab32(fA, Ap, TT, tid);     // A slab 0 (s-cols 0..31), latency covered by phase2 ALU

        int q = l & 3, rb = l >> 2;
        char* th = ng ? VtH1 : VtH0;
        char* tl = ng ? VtL1 : VtL0;
        #pragma unroll
        for (int mt = 0; mt < 2; ++mt){
            #pragma unroll
            for (int hf = 0; hf < 2; ++hf){
                int c = 32*mg + 16*mt + 8*hf + rb;
                uint32_t swc = (uint32_t)(c & 7) << 4;
                #pragma unroll
                for (int nt = 0; nt < 8; ++nt){
                    int sl = nt*8 + q*2;
                    float a = acc[mt][nt][2*hf], bq = acc[mt][nt][2*hf+1];
                    uint32_t hi = pack_bf(a, bq);
                    float la = a  - __uint_as_float(hi << 16);
                    float lb = bq - __uint_as_float(hi & 0xffff0000u);
                    uint32_t lo = pack_bf(la, lb);
                    uint32_t boff = (uint32_t)c*128u + (uint32_t)sl*2u;
                    uint32_t swz = boff ^ swc;
                    *(uint32_t*)(th + swz) = hi;
                    *(uint32_t*)(tl + swz) = lo;
                }
            }
        }
        #pragma unroll
        for (int i=0;i<2;i++)
            #pragma unroll
            for (int j=0;j<8;j++){ acc[i][j][0]=acc[i][j][1]=acc[i][j][2]=acc[i][j][3]=0.f; }

        char* a0 = base + 65536;
        cvt_sts32(a0, a0 + TILE32, fA, tid);
        ldg_slab32(fA, Ap + 32, TT, tid);    // A slab 1
        __syncthreads();

        // ---- Phase 3: D2[t, c] = sum_s A[t, s] * Vt[c, s]  (4 pipelined slabs) ----
        #pragma unroll 2
        for (int ss = 0; ss < 4; ++ss){
            char* cur = base + 65536 + (size_t)(ss&1)*2*TILE32;
            uint32_t sb = (uint32_t)ss*32;
            slab_mma32_bold(acc, smem_u32(cur), smem_u32(cur + TILE32),
                            smem_u32(sb < 64 ? VtH0 : VtH1),
                            smem_u32(sb < 64 ? VtL0 : VtL1),
                            (sb & 63u)*2u, mg, ng, l);
            if (ss < 3){
                char* nxt = base + 65536 + (size_t)((ss+1)&1)*2*TILE32;
                cvt_sts32(nxt, nxt + TILE32, fA, tid);
            }
            if (ss < 2) ldg_slab32(fA, Ap + (ss+2)*32, TT, tid);
            __syncthreads();
        }
    }

    // ---- Phase 4: store O[t, n0 + c] ----
    {
        int q = l & 3, rb = l >> 2;
        float* Ob = Out + (size_t)p*TT*HH + n0;
        #pragma unroll
        for (int mt = 0; mt < 2; ++mt){
            int t0 = 32*mg + 16*mt + rb, t1 = t0 + 8;
            #pragma unroll
            for (int nt = 0; nt < 8; ++nt){
                *(float2*)(Ob + (size_t)t0*HH + ng*64 + nt*8 + q*2) =
                    make_float2(acc[mt][nt][0], acc[mt][nt][1]);
                *(float2*)(Ob + (size_t)t1*HH + ng*64 + nt*8 + q*2) =
                    make_float2(acc[mt][nt][2], acc[mt][nt][3]);
            }
        }
    }
}

// =========================================================================================
extern "C" void kernel_launch(void* const* d_in, const int* in_sizes, int n_in,
                              void* d_out, int out_size){
    const float* node  = (const float*)d_in[0];
    const float* neigh = (const float*)d_in[1];
    int w = (n_in >= 8) ? 2 : 1;
    const float* Wq = (const float*)d_in[w+1];
    const float* Wk = (const float*)d_in[w+2];
    const float* Wv = (const float*)d_in[w+3];
    const float* Wb = (const float*)d_in[w+4];
    const float* bv = (const float*)d_in[w+5];

    float* out = (float*)d_out;
    const long long O_ELEMS = (long long)NPAIRS*TT*HH;
    const long long A_ELEMS = (long long)NPAIRS*TT*TT;
    float* Aout = ((long long)out_size >= O_ELEMS + A_ELEMS) ? (out + O_ELEMS) : nullptr;

    const int S_SMEM  = 8*TILE32 + 2048 + 1024;                 // 84992 B (x2 CTA = 166KB)
    const int VO_SMEM = 65536 + 4*TILE32 + 1024;                // 107520 B (x2 CTA = 210KB)
    cudaFuncSetAttribute(kernel_S_tc,  cudaFuncAttributeMaxDynamicSharedMemorySize, S_SMEM);
    cudaFuncSetAttribute(kernel_VO_tc, cudaFuncAttributeMaxDynamicSharedMemorySize, VO_SMEM);

    dim3 thr(256);
    sgemm_flat<0><<<dim3(64,2), thr>>>(node, Wq);        // g_q  = node @ Wq^T
    sgemm_flat<1><<<dim3(64,2), thr>>>(nullptr, Wb);     // g_t2 = g_q @ Wb
    sgemm_flat<2><<<dim3(64,2), thr>>>(nullptr, Wk);     // g_P  = g_t2 @ Wk
    kernel_S_tc <<<dim3(NPAIRS,1), thr, S_SMEM>>>(node, neigh, bv, Aout);
    kernel_VO_tc<<<dim3(NPAIRS,2), thr, VO_SMEM>>>(node, neigh, Wv, Aout, out);
}

// round 15
// speedup vs baseline: 1.4652x; 1.2344x over previous
#include <cuda_runtime.h>
#include <cstdint>

typedef unsigned long long ull;

#define BB 64
#define NN 16
#define TT 128
#define HH 256
#define NP1 17
#define NPAIRS (BB*NP1)   // 1088
#define LDT 132           // padded smem row stride for SIMT kernels
#define TPAD 64           // bytes/row of [128 x 32] bf16 tile; XOR ((row>>1)&3)<<4 -> conflict-free
#define TILE32 (128*TPAD) // 8192 B

// ---------------- scratch (static device globals; no runtime allocation) ----------------
__device__ float g_q  [BB*TT*HH];
__device__ float g_t2 [BB*TT*HH];
__device__ float g_P  [BB*TT*HH];
__device__ float g_Afb[(size_t)NPAIRS*TT*TT];

// =================== PTX helpers =========================================================
__device__ __forceinline__ uint32_t smem_u32(const void* p){
    uint32_t a;
    asm("{ .reg .u64 t; cvta.to.shared.u64 t, %1; cvt.u32.u64 %0, t; }" : "=r"(a) : "l"(p));
    return a;
}
// pack_bf(a,b): 32-bit word, low16 = bf16(a), high16 = bf16(b)
__device__ __forceinline__ uint32_t pack_bf(float a, float b){
    uint32_t r;
    asm("cvt.rn.satfinite.bf16x2.f32 %0, %1, %2;" : "=r"(r) : "f"(b), "f"(a));
    return r;
}
__device__ __forceinline__ void split2(float x, float y, uint32_t& h, uint32_t& l){
    h = pack_bf(x, y);
    float lx = x - __uint_as_float(h << 16);
    float ly = y - __uint_as_float(h & 0xffff0000u);
    l = pack_bf(lx, ly);
}
__device__ __forceinline__ void ldsm4(uint32_t r[4], uint32_t addr){
    asm volatile("ldmatrix.sync.aligned.m8n8.x4.shared.b16 {%0,%1,%2,%3}, [%4];"
        : "=r"(r[0]), "=r"(r[1]), "=r"(r[2]), "=r"(r[3]) : "r"(addr));
}
__device__ __forceinline__ void mma_bf16(float c[4], const uint32_t a[4],
                                         uint32_t b0, uint32_t b1){
    asm volatile(
        "mma.sync.aligned.m16n8k16.row.col.f32.bf16.bf16.f32 "
        "{%0,%1,%2,%3}, {%4,%5,%6,%7}, {%8,%9}, {%0,%1,%2,%3};"
        : "+f"(c[0]), "+f"(c[1]), "+f"(c[2]), "+f"(c[3])
        : "r"(a[0]), "r"(a[1]), "r"(a[2]), "r"(a[3]), "r"(b0), "r"(b1));
}

__device__ __forceinline__ const float* pair_base(int p, const float* node, const float* neigh){
    int b = p / NP1, n = p % NP1;
    return (n == 0) ? node  + (size_t)b*TT*HH
                    : neigh + (size_t)(b*NN + (n-1))*TT*HH;
}

// ---------------- staging: [128x32] fp32 slab -> regs -> split bf16 tiles (TPAD=64+XOR) --
// 256-thread variant: 16 floats/thread
__device__ __forceinline__ void ldg_slab_256(float4 f[4], const float* __restrict__ src,
                                             int ld, int tid){
    int row = tid >> 1, c0 = (tid & 1) * 16;
    const float* s = src + (size_t)row*ld + c0;
    f[0] = *(const float4*)(s);
    f[1] = *(const float4*)(s + 4);
    f[2] = *(const float4*)(s + 8);
    f[3] = *(const float4*)(s + 12);
}
__device__ __forceinline__ void cvt_sts_256(char* th, char* tl, const float4 f[4], int tid){
    int row = tid >> 1;
    uint32_t c0 = (uint32_t)(tid & 1) * 32u;
    uint32_t xorv = (((uint32_t)row >> 1) & 3u) << 4;
    uint32_t h[8], l[8];
    #pragma unroll
    for (int j = 0; j < 4; ++j){
        split2(f[j].x, f[j].y, h[2*j],   l[2*j]);
        split2(f[j].z, f[j].w, h[2*j+1], l[2*j+1]);
    }
    char* bh = th + row*TPAD;
    char* bl = tl + row*TPAD;
    *(uint4*)(bh + ( c0        ^ xorv)) = make_uint4(h[0],h[1],h[2],h[3]);
    *(uint4*)(bh + ((c0 + 16u) ^ xorv)) = make_uint4(h[4],h[5],h[6],h[7]);
    *(uint4*)(bl + ( c0        ^ xorv)) = make_uint4(l[0],l[1],l[2],l[3]);
    *(uint4*)(bl + ((c0 + 16u) ^ xorv)) = make_uint4(l[4],l[5],l[6],l[7]);
}
// 512-thread variant: 8 floats/thread
__device__ __forceinline__ void ldg_slab_512(float4 f[2], const float* __restrict__ src,
                                             int ld, int tid){
    int row = tid >> 2, c0 = (tid & 3) * 8;
    const float* s = src + (size_t)row*ld + c0;
    f[0] = *(const float4*)(s);
    f[1] = *(const float4*)(s + 4);
}
__device__ __forceinline__ void cvt_sts_512(char* th, char* tl, const float4 f[2], int tid){
    int row = tid >> 2;
    uint32_t c0 = (uint32_t)(tid & 3) * 16u;
    uint32_t xorv = (((uint32_t)row >> 1) & 3u) << 4;
    uint32_t h[4], l[4];
    split2(f[0].x, f[0].y, h[0], l[0]);
    split2(f[0].z, f[0].w, h[1], l[1]);
    split2(f[1].x, f[1].y, h[2], l[2]);
    split2(f[1].z, f[1].w, h[3], l[3]);
    *(uint4*)(th + row*TPAD + (c0 ^ xorv)) = make_uint4(h[0],h[1],h[2],h[3]);
    *(uint4*)(tl + row*TPAD + (c0 ^ xorv)) = make_uint4(l[0],l[1],l[2],l[3]);
}

// ---------------- one K=32 slab of split MMAs, 2D warp tiling (TPAD=64+XOR tiles) --------
// warp (mg, ng): rows [32*mg, +32) as 2 m-tiles, cols [64*ng, +64) as 8 n-tiles.
__device__ __forceinline__ void slab_mma32(float acc[2][8][4],
                                           uint32_t uAH, uint32_t uAL,
                                           uint32_t uBH, uint32_t uBL,
                                           int mg, int ng, int l){
    int r8 = l & 7;
    uint32_t xr = (((uint32_t)r8 >> 1) & 3u) << 4;   // (row>>1)&3 XOR — row bits 1,2 == r8 bits 1,2
    uint32_t aKadd = ((l>>4)&1) * 16;
    int rowA0 = 32*mg + ((l>>3)&1)*8 + r8;
    int rowBl = ((l>>4)&1)*8 + r8;
    uint32_t bKadd = ((l>>3)&1) * 16;
    #pragma unroll
    for (int ks = 0; ks < 2; ++ks){
        uint32_t ah[2][4], al[2][4];
        #pragma unroll
        for (int mt = 0; mt < 2; ++mt){
            uint32_t aoff = (uint32_t)(rowA0 + 16*mt)*TPAD + (((uint32_t)ks*32 + aKadd) ^ xr);
            ldsm4(ah[mt], uAH + aoff);
            ldsm4(al[mt], uAL + aoff);
        }
        #pragma unroll
        for (int ntp = 0; ntp < 4; ++ntp){
            uint32_t boff = (uint32_t)(ng*64 + ntp*16 + rowBl)*TPAD
                          + (((uint32_t)ks*32 + bKadd) ^ xr);
            uint32_t bh[4], bl[4];
            ldsm4(bh, uBH + boff);
            ldsm4(bl, uBL + boff);
            #pragma unroll
            for (int mt = 0; mt < 2; ++mt){
                mma_bf16(acc[mt][2*ntp],   ah[mt], bh[0], bh[1]);
                mma_bf16(acc[mt][2*ntp],   ah[mt], bl[0], bl[1]);
                mma_bf16(acc[mt][2*ntp],   al[mt], bh[0], bh[1]);
                mma_bf16(acc[mt][2*ntp+1], ah[mt], bh[2], bh[3]);
                mma_bf16(acc[mt][2*ntp+1], ah[mt], bl[2], bl[3]);
                mma_bf16(acc[mt][2*ntp+1], al[mt], bh[2], bh[3]);
            }
        }
    }
}

// same, but B operand in the OLD format: 128B rows, 64 k-cols, XOR (row&7)<<4 swizzle.
// srem2 = byte offset of this slab's k-base within the tile ((s_base % 64) * 2).
__device__ __forceinline__ void slab_mma32_bold(float acc[2][8][4],
                                                uint32_t uAH, uint32_t uAL,
                                                uint32_t uBH, uint32_t uBL, uint32_t srem2,
                                                int mg, int ng, int l){
    int r8 = l & 7;
    uint32_t xr = (((uint32_t)r8 >> 1) & 3u) << 4;
    uint32_t aKadd = ((l>>4)&1) * 16;
    int rowA0 = 32*mg + ((l>>3)&1)*8 + r8;
    int rowBl = ((l>>4)&1)*8 + r8;
    uint32_t bKadd = ((l>>3)&1) * 16;
    #pragma unroll
    for (int ks = 0; ks < 2; ++ks){
        uint32_t ah[2][4], al[2][4];
        #pragma unroll
        for (int mt = 0; mt < 2; ++mt){
            uint32_t aoff = (uint32_t)(rowA0 + 16*mt)*TPAD + (((uint32_t)ks*32 + aKadd) ^ xr);
            ldsm4(ah[mt], uAH + aoff);
            ldsm4(al[mt], uAL + aoff);
        }
        uint32_t kb = srem2 + (uint32_t)ks*32 + bKadd;
        #pragma unroll
        for (int ntp = 0; ntp < 4; ++ntp){
            int rowB = ng*64 + ntp*16 + rowBl;
            uint32_t boff = (uint32_t)rowB*128u + (kb ^ ((uint32_t)(rowB & 7) << 4));
            uint32_t bh[4], bl[4];
            ldsm4(bh, uBH + boff);
            ldsm4(bl, uBL + boff);
            #pragma unroll
            for (int mt = 0; mt < 2; ++mt){
                mma_bf16(acc[mt][2*ntp],   ah[mt], bh[0], bh[1]);
                mma_bf16(acc[mt][2*ntp],   ah[mt], bl[0], bl[1]);
                mma_bf16(acc[mt][2*ntp],   al[mt], bh[0], bh[1]);
                mma_bf16(acc[mt][2*ntp+1], ah[mt], bh[2], bh[3]);
                mma_bf16(acc[mt][2*ntp+1], ah[mt], bl[2], bl[3]);
                mma_bf16(acc[mt][2*ntp+1], al[mt], bh[2], bh[3]);
            }
        }
    }
}

// =================== SIMT fp32 machinery (K1..K3 weight chain, unchanged) ================
__device__ __forceinline__ void fma2(ull& d, ull a, ull b){
    asm("fma.rn.f32x2 %0, %1, %2, %0;" : "+l"(d) : "l"(a), "l"(b));
}
__device__ __forceinline__ ull pk2(float x, float y){
    ull r; asm("mov.b64 %0, {%1, %2};" : "=l"(r) : "f"(x), "f"(y)); return r;
}
__device__ __forceinline__ float2 upk(ull v){
    float2 f; asm("mov.b64 {%0, %1}, %2;" : "=f"(f.x), "=f"(f.y) : "l"(v)); return f;
}
struct F8 { float4 a, b; };
__device__ __forceinline__ F8 ldg_T(const float* __restrict__ src, int ld, int tid){
    int c4 = (tid & 3) * 4, r = tid >> 2;
    F8 f;
    f.a = *(const float4*)(src + (size_t)r*ld + c4);
    f.b = *(const float4*)(src + (size_t)(r+64)*ld + c4);
    return f;
}
__device__ __forceinline__ void sts_T(float (*dst)[LDT], F8 f, int tid){
    int c4 = (tid & 3) * 4, r = tid >> 2;
    dst[c4+0][r]    = f.a.x; dst[c4+1][r]    = f.a.y;
    dst[c4+2][r]    = f.a.z; dst[c4+3][r]    = f.a.w;
    dst[c4+0][r+64] = f.b.x; dst[c4+1][r+64] = f.b.y;
    dst[c4+2][r+64] = f.b.z; dst[c4+3][r+64] = f.b.w;
}
__device__ __forceinline__ F8 ldg_D(const float* __restrict__ src, int ld, int tid){
    int n4 = (tid & 15) * 4, k = tid >> 4;
    F8 f;
    f.a = *(const float4*)(src + (size_t)k*ld + n4);
    f.b = *(const float4*)(src + (size_t)k*ld + n4 + 64);
    return f;
}
__device__ __forceinline__ void sts_D(float (*dst)[LDT], F8 f, int tid){
    int n4 = (tid & 15) * 4, k = tid >> 4;
    *(float4*)(&dst[k][n4])      = f.a;
    *(float4*)(&dst[k][n4 + 64]) = f.b;
}
__device__ __forceinline__ void mm16(ull acc[8][4], const float (*As)[LDT],
                                     const float (*Bs)[LDT], int tx, int ty){
    #pragma unroll
    for (int k = 0; k < 16; ++k){
        float4 a0 = *(const float4*)(&As[k][ty*4]);
        float4 a1 = *(const float4*)(&As[k][64+ty*4]);
        float4 b0 = *(const float4*)(&Bs[k][tx*4]);
        float4 b1 = *(const float4*)(&Bs[k][64+tx*4]);
        ull bb0 = pk2(b0.x,b0.y), bb1 = pk2(b0.z,b0.w);
        ull bb2 = pk2(b1.x,b1.y), bb3 = pk2(b1.z,b1.w);
        float av[8] = {a0.x,a0.y,a0.z,a0.w,a1.x,a1.y,a1.z,a1.w};
        #pragma unroll
        for (int i = 0; i < 8; ++i){
            ull ad = pk2(av[i], av[i]);
            fma2(acc[i][0], ad, bb0);
            fma2(acc[i][1], ad, bb1);
            fma2(acc[i][2], ad, bb2);
            fma2(acc[i][3], ad, bb3);
        }
    }
}
__device__ __forceinline__ int row_of(int i, int ty){
    return (i < 4) ? (ty*4 + i) : (64 + ty*4 + (i-4));
}

// ================= K1..K3: flat [8192,256] x [256,256] GEMM chain (SIMT) =================
template<int STEP>
__global__ void __launch_bounds__(256, 2) sgemm_flat(const float* __restrict__ Ain,
                                                     const float* __restrict__ W){
    __shared__ __align__(16) float As[2][16][LDT], Bs[2][16][LDT];
    int tid = threadIdx.x, tx = tid & 15, ty = tid >> 4;
    const float* A = (STEP == 0) ? Ain : (STEP == 1 ? g_q : g_t2);
    float*       C = (STEP == 0) ? g_q : (STEP == 1 ? g_t2 : g_P);
    const float* Ab = A + (size_t)blockIdx.x * 128 * HH;
    int n0 = blockIdx.y * 128;
    const float* Bb = (STEP == 0) ? W + (size_t)n0*HH : W + n0;

    ull acc[8][4];
    #pragma unroll
    for (int i=0;i<8;i++){ acc[i][0]=acc[i][1]=acc[i][2]=acc[i][3]=0ULL; }

    F8 ra = ldg_T(Ab, HH, tid);
    F8 rb = (STEP == 0) ? ldg_T(Bb, HH, tid) : ldg_D(Bb, HH, tid);
    sts_T(As[0], ra, tid);
    if (STEP == 0) sts_T(Bs[0], rb, tid); else sts_D(Bs[0], rb, tid);
    __syncthreads();

    #pragma unroll 2
    for (int s = 0; s < 16; ++s){
        if (s < 15){
            ra = ldg_T(Ab + (s+1)*16, HH, tid);
            rb = (STEP == 0) ? ldg_T(Bb + (s+1)*16, HH, tid)
                             : ldg_D(Bb + (size_t)(s+1)*16*HH, HH, tid);
        }
        mm16(acc, As[s&1], Bs[s&1], tx, ty);
        if (s < 15){
            sts_T(As[(s+1)&1], ra, tid);
            if (STEP == 0) sts_T(Bs[(s+1)&1], rb, tid); else sts_D(Bs[(s+1)&1], rb, tid);
        }
        __syncthreads();
    }

    float* Cb = C + (size_t)blockIdx.x*128*HH + n0;
    #pragma unroll
    for (int i=0;i<8;i++){
        int row = row_of(i, ty);
        float2 p0=upk(acc[i][0]), p1=upk(acc[i][1]), p2=upk(acc[i][2]), p3=upk(acc[i][3]);
        *(float4*)(Cb + (size_t)row*HH + tx*4)      = make_float4(p0.x,p0.y,p1.x,p1.y);
        *(float4*)(Cb + (size_t)row*HH + 64 + tx*4) = make_float4(p2.x,p2.y,p3.x,p3.y);
    }
}

// ================= K4 (tensor): S = P_b @ X_p^T (+bias) -> softmax -> A ==================
__global__ void __launch_bounds__(256, 2) kernel_S_tc(const float* __restrict__ node,
                                                      const float* __restrict__ neigh,
                                                      const float* __restrict__ bias,
                                                      float* Aout){
    extern __shared__ char sm[];
    char* base = (char*)(((uintptr_t)sm + 1023) & ~(uintptr_t)1023);
    // buf b at base + b*4*TILE32 : [PH][PL][XH][XL]
    float* xchM = (float*)(base + 8*TILE32);     // [2][128]
    float* xchS = xchM + 256;                    // [2][128]

    int tid = threadIdx.x, w = tid >> 5, l = tid & 31;
    int mg = w >> 1, ng = w & 1;
    int p = blockIdx.x, b = p / NP1;
    const float* P = g_P + (size_t)b*TT*HH;
    const float* X = pair_base(p, node, neigh);
    float* Ao = Aout ? Aout : g_Afb;

    float acc[2][8][4];
    #pragma unroll
    for (int i=0;i<2;i++)
        #pragma unroll
        for (int j=0;j<8;j++){ acc[i][j][0]=acc[i][j][1]=acc[i][j][2]=acc[i][j][3]=0.f; }

    float4 fP[4], fX[4];
    ldg_slab_256(fP, P, HH, tid);
    ldg_slab_256(fX, X, HH, tid);
    cvt_sts_256(base + 0*TILE32, base + 1*TILE32, fP, tid);
    cvt_sts_256(base + 2*TILE32, base + 3*TILE32, fX, tid);
    ldg_slab_256(fP, P + 32, HH, tid);
    ldg_slab_256(fX, X + 32, HH, tid);
    __syncthreads();

    #pragma unroll 2
    for (int s = 0; s < 8; ++s){
        char* cur = base + (size_t)(s&1)*4*TILE32;
        uint32_t u = smem_u32(cur);
        slab_mma32(acc, u, u + TILE32, u + 2*TILE32, u + 3*TILE32, mg, ng, l);
        if (s < 7){
            char* nxt = base + (size_t)((s+1)&1)*4*TILE32;
            cvt_sts_256(nxt + 0*TILE32, nxt + 1*TILE32, fP, tid);
            cvt_sts_256(nxt + 2*TILE32, nxt + 3*TILE32, fX, tid);
        }
        if (s < 6){
            ldg_slab_256(fP, P + (s+2)*32, HH, tid);
            ldg_slab_256(fX, X + (s+2)*32, HH, tid);
        }
        __syncthreads();
    }

    // epilogue: bias + softmax over 128 cols, ng-pair combine via smem
    int q = l & 3, rb = l >> 2;
    #pragma unroll
    for (int nt = 0; nt < 8; ++nt){
        float2 bb = *(const float2*)(bias + ng*64 + nt*8 + q*2);
        #pragma unroll
        for (int mt = 0; mt < 2; ++mt){
            acc[mt][nt][0] += bb.x; acc[mt][nt][1] += bb.y;
            acc[mt][nt][2] += bb.x; acc[mt][nt][3] += bb.y;
        }
    }
    float mx[2][2];
    #pragma unroll
    for (int mt = 0; mt < 2; ++mt){
        mx[mt][0] = -1e30f; mx[mt][1] = -1e30f;
        #pragma unroll
        for (int nt = 0; nt < 8; ++nt){
            mx[mt][0] = fmaxf(mx[mt][0], fmaxf(acc[mt][nt][0], acc[mt][nt][1]));
            mx[mt][1] = fmaxf(mx[mt][1], fmaxf(acc[mt][nt][2], acc[mt][nt][3]));
        }
        #pragma unroll
        for (int o = 1; o <= 2; o <<= 1){
            mx[mt][0] = fmaxf(mx[mt][0], __shfl_xor_sync(0xffffffffu, mx[mt][0], o));
            mx[mt][1] = fmaxf(mx[mt][1], __shfl_xor_sync(0xffffffffu, mx[mt][1], o));
        }
    }
    if (q == 0){
        #pragma unroll
        for (int mt = 0; mt < 2; ++mt){
            xchM[ng*128 + 32*mg + 16*mt + rb]     = mx[mt][0];
            xchM[ng*128 + 32*mg + 16*mt + 8 + rb] = mx[mt][1];
        }
    }
    __syncthreads();
    float sum[2][2];
    #pragma unroll
    for (int mt = 0; mt < 2; ++mt){
        int r0 = 32*mg + 16*mt + rb;
        float m0 = fmaxf(xchM[r0],     xchM[128 + r0]);
        float m1 = fmaxf(xchM[r0 + 8], xchM[128 + r0 + 8]);
        sum[mt][0] = 0.f; sum[mt][1] = 0.f;
        #pragma unroll
        for (int nt = 0; nt < 8; ++nt){
            acc[mt][nt][0] = __expf(acc[mt][nt][0] - m0); sum[mt][0] += acc[mt][nt][0];
            acc[mt][nt][1] = __expf(acc[mt][nt][1] - m0); sum[mt][0] += acc[mt][nt][1];
            acc[mt][nt][2] = __expf(acc[mt][nt][2] - m1); sum[mt][1] += acc[mt][nt][2];
            acc[mt][nt][3] = __expf(acc[mt][nt][3] - m1); sum[mt][1] += acc[mt][nt][3];
        }
        #pragma unroll
        for (int o = 1; o <= 2; o <<= 1){
            sum[mt][0] += __shfl_xor_sync(0xffffffffu, sum[mt][0], o);
            sum[mt][1] += __shfl_xor_sync(0xffffffffu, sum[mt][1], o);
        }
    }
    if (q == 0){
        #pragma unroll
        for (int mt = 0; mt < 2; ++mt){
            xchS[ng*128 + 32*mg + 16*mt + rb]     = sum[mt][0];
            xchS[ng*128 + 32*mg + 16*mt + 8 + rb] = sum[mt][1];
        }
    }
    __syncthreads();
    float* Ap = Ao + (size_t)p*TT*TT;
    #pragma unroll
    for (int mt = 0; mt < 2; ++mt){
        int r0 = 32*mg + 16*mt + rb, r1 = r0 + 8;
        float i0 = 1.f / (xchS[r0] + xchS[128 + r0]);
        float i1 = 1.f / (xchS[r1] + xchS[128 + r1]);
        #pragma unroll
        for (int nt = 0; nt < 8; ++nt){
            *(float2*)(Ap + (size_t)r0*TT + ng*64 + nt*8 + q*2) =
                make_float2(acc[mt][nt][0]*i0, acc[mt][nt][1]*i0);
            *(float2*)(Ap + (size_t)r1*TT + ng*64 + nt*8 + q*2) =
                make_float2(acc[mt][nt][2]*i1, acc[mt][nt][3]*i1);
        }
    }
}

// ================= K5 (tensor, MERGED): both 128-col chunks in ONE 512-thread CTA ========
// wg0 (warps 0-7): chunk 0 (Wv rows 0-127); wg1 (warps 8-15): chunk 1 (rows 128-255).
// Phase1 stages {W0, W1, X} per slab (X shared!); phase3 stages A once (shared!).
__global__ void __launch_bounds__(512, 1) kernel_VO_tc(const float* __restrict__ node,
                                                       const float* __restrict__ neigh,
                                                       const float* __restrict__ Wv,
                                                       const float* Ain,
                                                       float* __restrict__ Out){
    extern __shared__ char sm[];
    char* base = (char*)(((uintptr_t)sm + 1023) & ~(uintptr_t)1023);
    // phase1 staging: buf b at base + b*6*TILE32 : [W0H][W0L][W1H][W1L][XH][XL]  (98304 B)
    // Vt (overwrites staging after phase1): chunk c at base + c*65536 : [Hs0][Ls0][Hs1][Ls1]
    //    (old 128B/XOR format, 16384 each; total 131072 B)
    // phase3 A staging: buf b at base + 131072 + b*2*TILE32                      (32768 B)
    int tid = threadIdx.x, w = tid >> 5, l = tid & 31;
    int wg = w >> 3, wl = w & 7, mg = wl >> 1, ng = wl & 1;
    int p = blockIdx.x;
    const float* X  = pair_base(p, node, neigh);
    const float* W0 = Wv;
    const float* W1 = Wv + (size_t)128*HH;
    const float* Ap = (Ain ? Ain : (const float*)g_Afb) + (size_t)p*TT*TT;

    float acc[2][8][4];
    #pragma unroll
    for (int i=0;i<2;i++)
        #pragma unroll
        for (int j=0;j<8;j++){ acc[i][j][0]=acc[i][j][1]=acc[i][j][2]=acc[i][j][3]=0.f; }

    // ---- Phase 1: Vt_wg[c, s] = sum_h Wv[wg*128+c, h] * X[s, h]  (8 pipelined slabs) ----
    {
        float4 fW0[2], fW1[2], fX[2];
        ldg_slab_512(fW0, W0, HH, tid);
        ldg_slab_512(fW1, W1, HH, tid);
        ldg_slab_512(fX,  X,  HH, tid);
        cvt_sts_512(base + 0*TILE32, base + 1*TILE32, fW0, tid);
        cvt_sts_512(base + 2*TILE32, base + 3*TILE32, fW1, tid);
        cvt_sts_512(base + 4*TILE32, base + 5*TILE32, fX,  tid);
        ldg_slab_512(fW0, W0 + 32, HH, tid);
        ldg_slab_512(fW1, W1 + 32, HH, tid);
        ldg_slab_512(fX,  X  + 32, HH, tid);
        __syncthreads();

        #pragma unroll 2
        for (int s = 0; s < 8; ++s){
            char* cur = base + (size_t)(s&1)*6*TILE32;
            uint32_t uA = smem_u32(cur) + (uint32_t)wg*2*TILE32;   // W_wg hi
            uint32_t uB = smem_u32(cur) + 4*TILE32;                // X hi
            slab_mma32(acc, uA, uA + TILE32, uB, uB + TILE32, mg, ng, l);
            if (s < 7){
                char* nxt = base + (size_t)((s+1)&1)*6*TILE32;
                cvt_sts_512(nxt + 0*TILE32, nxt + 1*TILE32, fW0, tid);
                cvt_sts_512(nxt + 2*TILE32, nxt + 3*TILE32, fW1, tid);
                cvt_sts_512(nxt + 4*TILE32, nxt + 5*TILE32, fX,  tid);
            }
            if (s < 6){
                ldg_slab_512(fW0, W0 + (s+2)*32, HH, tid);
                ldg_slab_512(fW1, W1 + (s+2)*32, HH, tid);
                ldg_slab_512(fX,  X  + (s+2)*32, HH, tid);
            }
            __syncthreads();
        }
    }

    // ---- Phase 2: split-convert D1 (regs) into Vt tiles + stage A slab 0 ----
    {
        float4 fA[2];
        ldg_slab_512(fA, Ap, TT, tid);   // A slab 0, latency covered by phase-2 ALU

        int q = l & 3, rb = l >> 2;
        char* VtBase = base + (size_t)wg*65536;
        char* th = VtBase + (ng ? 32768 : 0);
        char* tl = th + 16384;
        #pragma unroll
        for (int mt = 0; mt < 2; ++mt){
            #pragma unroll
            for (int hf = 0; hf < 2; ++hf){
                int c = 32*mg + 16*mt + 8*hf + rb;
                uint32_t swc = (uint32_t)(c & 7) << 4;
                #pragma unroll
                for (int nt = 0; nt < 8; ++nt){
                    int sl = nt*8 + q*2;
                    float a = acc[mt][nt][2*hf], bq = acc[mt][nt][2*hf+1];
                    uint32_t hi = pack_bf(a, bq);
                    float la = a  - __uint_as_float(hi << 16);
                    float lb = bq - __uint_as_float(hi & 0xffff0000u);
                    uint32_t lo = pack_bf(la, lb);
                    uint32_t boff = (uint32_t)c*128u + (uint32_t)sl*2u;
                    uint32_t swz = boff ^ swc;
                    *(uint32_t*)(th + swz) = hi;
                    *(uint32_t*)(tl + swz) = lo;
                }
            }
        }
        #pragma unroll
        for (int i=0;i<2;i++)
            #pragma unroll
            for (int j=0;j<8;j++){ acc[i][j][0]=acc[i][j][1]=acc[i][j][2]=acc[i][j][3]=0.f; }

        char* a0 = base + 131072;
        cvt_sts_512(a0, a0 + TILE32, fA, tid);
        ldg_slab_512(fA, Ap + 32, TT, tid);   // A slab 1
        __syncthreads();

        // ---- Phase 3: O[t, wg*128 + c] = sum_s A[t, s] * Vt_wg[c, s]  (4 pipelined slabs)
        #pragma unroll 2
        for (int ss = 0; ss < 4; ++ss){
            char* cur = base + 131072 + (size_t)(ss&1)*2*TILE32;
            uint32_t sb = (uint32_t)ss*32;
            uint32_t uBH = smem_u32(base + (size_t)wg*65536 + (sb < 64 ? 0 : 32768));
            uint32_t uAH = smem_u32(cur);
            slab_mma32_bold(acc, uAH, uAH + TILE32, uBH, uBH + 16384,
                            (sb & 63u)*2u, mg, ng, l);
            if (ss < 3){
                char* nxt = base + 131072 + (size_t)((ss+1)&1)*2*TILE32;
                cvt_sts_512(nxt, nxt + TILE32, fA, tid);
            }
            if (ss < 2) ldg_slab_512(fA, Ap + (ss+2)*32, TT, tid);
            __syncthreads();
        }
    }

    // ---- Phase 4: store O[t, wg*128 + ng*64 + ...] ----
    {
        int q = l & 3, rb = l >> 2;
        float* Ob = Out + (size_t)p*TT*HH + wg*128;
        #pragma unroll
        for (int mt = 0; mt < 2; ++mt){
            int t0 = 32*mg + 16*mt + rb, t1 = t0 + 8;
            #pragma unroll
            for (int nt = 0; nt < 8; ++nt){
                *(float2*)(Ob + (size_t)t0*HH + ng*64 + nt*8 + q*2) =
                    make_float2(acc[mt][nt][0], acc[mt][nt][1]);
                *(float2*)(Ob + (size_t)t1*HH + ng*64 + nt*8 + q*2) =
                    make_float2(acc[mt][nt][2], acc[mt][nt][3]);
            }
        }
    }
}

// =========================================================================================
extern "C" void kernel_launch(void* const* d_in, const int* in_sizes, int n_in,
                              void* d_out, int out_size){
    const float* node  = (const float*)d_in[0];
    const float* neigh = (const float*)d_in[1];
    int w = (n_in >= 8) ? 2 : 1;
    const float* Wq = (const float*)d_in[w+1];
    const float* Wk = (const float*)d_in[w+2];
    const float* Wv = (const float*)d_in[w+3];
    const float* Wb = (const float*)d_in[w+4];
    const float* bv = (const float*)d_in[w+5];

    float* out = (float*)d_out;
    const long long O_ELEMS = (long long)NPAIRS*TT*HH;
    const long long A_ELEMS = (long long)NPAIRS*TT*TT;
    float* Aout = ((long long)out_size >= O_ELEMS + A_ELEMS) ? (out + O_ELEMS) : nullptr;

    const int S_SMEM  = 8*TILE32 + 2048 + 1024;       // 68608 B (x2 CTA = 137KB)
    const int VO_SMEM = 131072 + 4*TILE32 + 1024;     // 164864 B (1 CTA)
    cudaFuncSetAttribute(kernel_S_tc,  cudaFuncAttributeMaxDynamicSharedMemorySize, S_SMEM);
    cudaFuncSetAttribute(kernel_VO_tc, cudaFuncAttributeMaxDynamicSharedMemorySize, VO_SMEM);

    sgemm_flat<0><<<dim3(64,2), 256>>>(node, Wq);        // g_q  = node @ Wq^T
    sgemm_flat<1><<<dim3(64,2), 256>>>(nullptr, Wb);     // g_t2 = g_q @ Wb
    sgemm_flat<2><<<dim3(64,2), 256>>>(nullptr, Wk);     // g_P  = g_t2 @ Wk
    kernel_S_tc <<<dim3(NPAIRS,1), 256, S_SMEM>>>(node, neigh, bv, Aout);
    kernel_VO_tc<<<dim3(NPAIRS,1), 512, VO_SMEM>>>(node, neigh, Wv, Aout, out);
}

// round 16
// speedup vs baseline: 1.4984x; 1.0227x over previous
#include <cuda_runtime.h>
#include <cstdint>

typedef unsigned long long ull;

#define BB 64
#define NN 16
#define TT 128
#define HH 256
#define NP1 17
#define NPAIRS (BB*NP1)   // 1088
#define LDT 132           // padded smem row stride for SIMT kernels
#define TPAD 64           // bytes/row of [128 x 32] bf16 tile; XOR ((row>>1)&3)<<4 -> conflict-free
#define TILE32 (128*TPAD) // 8192 B

// ---------------- scratch (static device globals; no runtime allocation) ----------------
__device__ float g_q  [BB*TT*HH];
__device__ float g_t2 [BB*TT*HH];
__device__ float g_P  [BB*TT*HH];

// =================== PTX helpers =========================================================
__device__ __forceinline__ uint32_t smem_u32(const void* p){
    uint32_t a;
    asm("{ .reg .u64 t; cvta.to.shared.u64 t, %1; cvt.u32.u64 %0, t; }" : "=r"(a) : "l"(p));
    return a;
}
__device__ __forceinline__ uint32_t pack_bf(float a, float b){
    uint32_t r;
    asm("cvt.rn.satfinite.bf16x2.f32 %0, %1, %2;" : "=r"(r) : "f"(b), "f"(a));
    return r;
}
__device__ __forceinline__ void split2(float x, float y, uint32_t& h, uint32_t& l){
    h = pack_bf(x, y);
    float lx = x - __uint_as_float(h << 16);
    float ly = y - __uint_as_float(h & 0xffff0000u);
    l = pack_bf(lx, ly);
}
__device__ __forceinline__ void ldsm4(uint32_t r[4], uint32_t addr){
    asm volatile("ldmatrix.sync.aligned.m8n8.x4.shared.b16 {%0,%1,%2,%3}, [%4];"
        : "=r"(r[0]), "=r"(r[1]), "=r"(r[2]), "=r"(r[3]) : "r"(addr));
}
__device__ __forceinline__ void mma_bf16(float c[4], const uint32_t a[4],
                                         uint32_t b0, uint32_t b1){
    asm volatile(
        "mma.sync.aligned.m16n8k16.row.col.f32.bf16.bf16.f32 "
        "{%0,%1,%2,%3}, {%4,%5,%6,%7}, {%8,%9}, {%0,%1,%2,%3};"
        : "+f"(c[0]), "+f"(c[1]), "+f"(c[2]), "+f"(c[3])
        : "r"(a[0]), "r"(a[1]), "r"(a[2]), "r"(a[3]), "r"(b0), "r"(b1));
}

__device__ __forceinline__ const float* pair_base(int p, const float* node, const float* neigh){
    int b = p / NP1, n = p % NP1;
    return (n == 0) ? node  + (size_t)b*TT*HH
                    : neigh + (size_t)(b*NN + (n-1))*TT*HH;
}

// ---------------- staging: [128x32] fp32 slab -> regs -> split bf16 tiles (TPAD=64+XOR) --
__device__ __forceinline__ void ldg_slab_512(float4 f[2], const float* __restrict__ src,
                                             int ld, int tid){
    int row = tid >> 2, c0 = (tid & 3) * 8;
    const float* s = src + (size_t)row*ld + c0;
    f[0] = *(const float4*)(s);
    f[1] = *(const float4*)(s + 4);
}
__device__ __forceinline__ void cvt_sts_512(char* th, char* tl, const float4 f[2], int tid){
    int row = tid >> 2;
    uint32_t c0 = (uint32_t)(tid & 3) * 16u;
    uint32_t xorv = (((uint32_t)row >> 1) & 3u) << 4;
    uint32_t h[4], l[4];
    split2(f[0].x, f[0].y, h[0], l[0]);
    split2(f[0].z, f[0].w, h[1], l[1]);
    split2(f[1].x, f[1].y, h[2], l[2]);
    split2(f[1].z, f[1].w, h[3], l[3]);
    *(uint4*)(th + row*TPAD + (c0 ^ xorv)) = make_uint4(h[0],h[1],h[2],h[3]);
    *(uint4*)(tl + row*TPAD + (c0 ^ xorv)) = make_uint4(l[0],l[1],l[2],l[3]);
}

// ---------------- K=32 slab of split MMAs, 32x64 warp tile (TPAD=64+XOR tiles) -----------
__device__ __forceinline__ void slab_mma32(float acc[2][8][4],
                                           uint32_t uAH, uint32_t uAL,
                                           uint32_t uBH, uint32_t uBL,
                                           int mg, int ng, int l){
    int r8 = l & 7;
    uint32_t xr = (((uint32_t)r8 >> 1) & 3u) << 4;
    uint32_t aKadd = ((l>>4)&1) * 16;
    int rowA0 = 32*mg + ((l>>3)&1)*8 + r8;
    int rowBl = ((l>>4)&1)*8 + r8;
    uint32_t bKadd = ((l>>3)&1) * 16;
    #pragma unroll
    for (int ks = 0; ks < 2; ++ks){
        uint32_t ah[2][4], al[2][4];
        #pragma unroll
        for (int mt = 0; mt < 2; ++mt){
            uint32_t aoff = (uint32_t)(rowA0 + 16*mt)*TPAD + (((uint32_t)ks*32 + aKadd) ^ xr);
            ldsm4(ah[mt], uAH + aoff);
            ldsm4(al[mt], uAL + aoff);
        }
        #pragma unroll
        for (int ntp = 0; ntp < 4; ++ntp){
            uint32_t boff = (uint32_t)(ng*64 + ntp*16 + rowBl)*TPAD
                          + (((uint32_t)ks*32 + bKadd) ^ xr);
            uint32_t bh[4], bl[4];
            ldsm4(bh, uBH + boff);
            ldsm4(bl, uBL + boff);
            #pragma unroll
            for (int mt = 0; mt < 2; ++mt){
                mma_bf16(acc[mt][2*ntp],   ah[mt], bh[0], bh[1]);
                mma_bf16(acc[mt][2*ntp],   ah[mt], bl[0], bl[1]);
                mma_bf16(acc[mt][2*ntp],   al[mt], bh[0], bh[1]);
                mma_bf16(acc[mt][2*ntp+1], ah[mt], bh[2], bh[3]);
                mma_bf16(acc[mt][2*ntp+1], ah[mt], bl[2], bl[3]);
                mma_bf16(acc[mt][2*ntp+1], al[mt], bh[2], bh[3]);
            }
        }
    }
}

// ---------------- K=32 slab, 32x32 warp tile (S phase; 4x4 warp grid) --------------------
__device__ __forceinline__ void slab_mma32_s(float acc[2][4][4],
                                             uint32_t uAH, uint32_t uAL,
                                             uint32_t uBH, uint32_t uBL,
                                             int smg, int sng, int l){
    int r8 = l & 7;
    uint32_t xr = (((uint32_t)r8 >> 1) & 3u) << 4;
    uint32_t aKadd = ((l>>4)&1) * 16;
    int rowA0 = 32*smg + ((l>>3)&1)*8 + r8;
    int rowBl = ((l>>4)&1)*8 + r8;
    uint32_t bKadd = ((l>>3)&1) * 16;
    #pragma unroll
    for (int ks = 0; ks < 2; ++ks){
        uint32_t ah[2][4], al[2][4];
        #pragma unroll
        for (int mt = 0; mt < 2; ++mt){
            uint32_t aoff = (uint32_t)(rowA0 + 16*mt)*TPAD + (((uint32_t)ks*32 + aKadd) ^ xr);
            ldsm4(ah[mt], uAH + aoff);
            ldsm4(al[mt], uAL + aoff);
        }
        #pragma unroll
        for (int ntp = 0; ntp < 2; ++ntp){
            uint32_t boff = (uint32_t)(sng*32 + ntp*16 + rowBl)*TPAD
                          + (((uint32_t)ks*32 + bKadd) ^ xr);
            uint32_t bh[4], bl[4];
            ldsm4(bh, uBH + boff);
            ldsm4(bl, uBL + boff);
            #pragma unroll
            for (int mt = 0; mt < 2; ++mt){
                mma_bf16(acc[mt][2*ntp],   ah[mt], bh[0], bh[1]);
                mma_bf16(acc[mt][2*ntp],   ah[mt], bl[0], bl[1]);
                mma_bf16(acc[mt][2*ntp],   al[mt], bh[0], bh[1]);
                mma_bf16(acc[mt][2*ntp+1], ah[mt], bh[2], bh[3]);
                mma_bf16(acc[mt][2*ntp+1], ah[mt], bl[2], bl[3]);
                mma_bf16(acc[mt][2*ntp+1], al[mt], bh[2], bh[3]);
            }
        }
    }
}

// ---------------- K=32 slab, A new-format / B OLD-format (128B rows + (r&7)<<4 XOR) ------
__device__ __forceinline__ void slab_mma32_bold(float acc[2][8][4],
                                                uint32_t uAH, uint32_t uAL,
                                                uint32_t uBH, uint32_t uBL, uint32_t srem2,
                                                int mg, int ng, int l){
    int r8 = l & 7;
    uint32_t xr = (((uint32_t)r8 >> 1) & 3u) << 4;
    uint32_t aKadd = ((l>>4)&1) * 16;
    int rowA0 = 32*mg + ((l>>3)&1)*8 + r8;
    int rowBl = ((l>>4)&1)*8 + r8;
    uint32_t bKadd = ((l>>3)&1) * 16;
    #pragma unroll
    for (int ks = 0; ks < 2; ++ks){
        uint32_t ah[2][4], al[2][4];
        #pragma unroll
        for (int mt = 0; mt < 2; ++mt){
            uint32_t aoff = (uint32_t)(rowA0 + 16*mt)*TPAD + (((uint32_t)ks*32 + aKadd) ^ xr);
            ldsm4(ah[mt], uAH + aoff);
            ldsm4(al[mt], uAL + aoff);
        }
        uint32_t kb = srem2 + (uint32_t)ks*32 + bKadd;
        #pragma unroll
        for (int ntp = 0; ntp < 4; ++ntp){
            int rowB = ng*64 + ntp*16 + rowBl;
            uint32_t boff = (uint32_t)rowB*128u + (kb ^ ((uint32_t)(rowB & 7) << 4));
            uint32_t bh[4], bl[4];
            ldsm4(bh, uBH + boff);
            ldsm4(bl, uBL + boff);
            #pragma unroll
            for (int mt = 0; mt < 2; ++mt){
                mma_bf16(acc[mt][2*ntp],   ah[mt], bh[0], bh[1]);
                mma_bf16(acc[mt][2*ntp],   ah[mt], bl[0], bl[1]);
                mma_bf16(acc[mt][2*ntp],   al[mt], bh[0], bh[1]);
                mma_bf16(acc[mt][2*ntp+1], ah[mt], bh[2], bh[3]);
                mma_bf16(acc[mt][2*ntp+1], ah[mt], bl[2], bl[3]);
                mma_bf16(acc[mt][2*ntp+1], al[mt], bh[2], bh[3]);
            }
        }
    }
}

// =================== SIMT fp32 machinery (K1..K3 weight chain, unchanged) ================
__device__ __forceinline__ void fma2(ull& d, ull a, ull b){
    asm("fma.rn.f32x2 %0, %1, %2, %0;" : "+l"(d) : "l"(a), "l"(b));
}
__device__ __forceinline__ ull pk2(float x, float y){
    ull r; asm("mov.b64 %0, {%1, %2};" : "=l"(r) : "f"(x), "f"(y)); return r;
}
__device__ __forceinline__ float2 upk(ull v){
    float2 f; asm("mov.b64 {%0, %1}, %2;" : "=f"(f.x), "=f"(f.y) : "l"(v)); return f;
}
struct F8 { float4 a, b; };
__device__ __forceinline__ F8 ldg_T(const float* __restrict__ src, int ld, int tid){
    int c4 = (tid & 3) * 4, r = tid >> 2;
    F8 f;
    f.a = *(const float4*)(src + (size_t)r*ld + c4);
    f.b = *(const float4*)(src + (size_t)(r+64)*ld + c4);
    return f;
}
__device__ __forceinline__ void sts_T(float (*dst)[LDT], F8 f, int tid){
    int c4 = (tid & 3) * 4, r = tid >> 2;
    dst[c4+0][r]    = f.a.x; dst[c4+1][r]    = f.a.y;
    dst[c4+2][r]    = f.a.z; dst[c4+3][r]    = f.a.w;
    dst[c4+0][r+64] = f.b.x; dst[c4+1][r+64] = f.b.y;
    dst[c4+2][r+64] = f.b.z; dst[c4+3][r+64] = f.b.w;
}
__device__ __forceinline__ F8 ldg_D(const float* __restrict__ src, int ld, int tid){
    int n4 = (tid & 15) * 4, k = tid >> 4;
    F8 f;
    f.a = *(const float4*)(src + (size_t)k*ld + n4);
    f.b = *(const float4*)(src + (size_t)k*ld + n4 + 64);
    return f;
}
__device__ __forceinline__ void sts_D(float (*dst)[LDT], F8 f, int tid){
    int n4 = (tid & 15) * 4, k = tid >> 4;
    *(float4*)(&dst[k][n4])      = f.a;
    *(float4*)(&dst[k][n4 + 64]) = f.b;
}
__device__ __forceinline__ void mm16(ull acc[8][4], const float (*As)[LDT],
                                     const float (*Bs)[LDT], int tx, int ty){
    #pragma unroll
    for (int k = 0; k < 16; ++k){
        float4 a0 = *(const float4*)(&As[k][ty*4]);
        float4 a1 = *(const float4*)(&As[k][64+ty*4]);
        float4 b0 = *(const float4*)(&Bs[k][tx*4]);
        float4 b1 = *(const float4*)(&Bs[k][64+tx*4]);
        ull bb0 = pk2(b0.x,b0.y), bb1 = pk2(b0.z,b0.w);
        ull bb2 = pk2(b1.x,b1.y), bb3 = pk2(b1.z,b1.w);
        float av[8] = {a0.x,a0.y,a0.z,a0.w,a1.x,a1.y,a1.z,a1.w};
        #pragma unroll
        for (int i = 0; i < 8; ++i){
            ull ad = pk2(av[i], av[i]);
            fma2(acc[i][0], ad, bb0);
            fma2(acc[i][1], ad, bb1);
            fma2(acc[i][2], ad, bb2);
            fma2(acc[i][3], ad, bb3);
        }
    }
}
__device__ __forceinline__ int row_of(int i, int ty){
    return (i < 4) ? (ty*4 + i) : (64 + ty*4 + (i-4));
}

// ================= K1..K3: flat [8192,256] x [256,256] GEMM chain (SIMT) =================
template<int STEP>
__global__ void __launch_bounds__(256, 2) sgemm_flat(const float* __restrict__ Ain,
                                                     const float* __restrict__ W){
    __shared__ __align__(16) float As[2][16][LDT], Bs[2][16][LDT];
    int tid = threadIdx.x, tx = tid & 15, ty = tid >> 4;
    const float* A = (STEP == 0) ? Ain : (STEP == 1 ? g_q : g_t2);
    float*       C = (STEP == 0) ? g_q : (STEP == 1 ? g_t2 : g_P);
    const float* Ab = A + (size_t)blockIdx.x * 128 * HH;
    int n0 = blockIdx.y * 128;
    const float* Bb = (STEP == 0) ? W + (size_t)n0*HH : W + n0;

    ull acc[8][4];
    #pragma unroll
    for (int i=0;i<8;i++){ acc[i][0]=acc[i][1]=acc[i][2]=acc[i][3]=0ULL; }

    F8 ra = ldg_T(Ab, HH, tid);
    F8 rb = (STEP == 0) ? ldg_T(Bb, HH, tid) : ldg_D(Bb, HH, tid);
    sts_T(As[0], ra, tid);
    if (STEP == 0) sts_T(Bs[0], rb, tid); else sts_D(Bs[0], rb, tid);
    __syncthreads();

    #pragma unroll 2
    for (int s = 0; s < 16; ++s){
        if (s < 15){
            ra = ldg_T(Ab + (s+1)*16, HH, tid);
            rb = (STEP == 0) ? ldg_T(Bb + (s+1)*16, HH, tid)
                             : ldg_D(Bb + (size_t)(s+1)*16*HH, HH, tid);
        }
        mm16(acc, As[s&1], Bs[s&1], tx, ty);
        if (s < 15){
            sts_T(As[(s+1)&1], ra, tid);
            if (STEP == 0) sts_T(Bs[(s+1)&1], rb, tid); else sts_D(Bs[(s+1)&1], rb, tid);
        }
        __syncthreads();
    }

    float* Cb = C + (size_t)blockIdx.x*128*HH + n0;
    #pragma unroll
    for (int i=0;i<8;i++){
        int row = row_of(i, ty);
        float2 p0=upk(acc[i][0]), p1=upk(acc[i][1]), p2=upk(acc[i][2]), p3=upk(acc[i][3]);
        *(float4*)(Cb + (size_t)row*HH + tx*4)      = make_float4(p0.x,p0.y,p1.x,p1.y);
        *(float4*)(Cb + (size_t)row*HH + 64 + tx*4) = make_float4(p2.x,p2.y,p3.x,p3.y);
    }
}

// ================= FUSED attention kernel (512 threads, one CTA per pair) ================
// P1: Vt[c,s] = sum_h Wv[c,h] X[s,h]      (wg chunk split; staging @131072, 2x6 tiles)
// P2: Vt -> smem [0,131072) (old fmt)     (+ stage S slab 0)
// P3: S = P @ X^T                          (16 warps, 4x4 grid of 32x32; staging @131072)
// P4: softmax (4-group combine) -> A fp32 gmem (if output) + A split tiles @131072
// P5: O = A @ Vt                           (all operands resident; no staging, no syncs)
__global__ void __launch_bounds__(512, 1) kernel_att(const float* __restrict__ node,
                                                     const float* __restrict__ neigh,
                                                     const float* __restrict__ Wv,
                                                     const float* __restrict__ bias,
                                                     float* Aout,
                                                     float* __restrict__ Out){
    extern __shared__ char sm[];
    char* base = (char*)(((uintptr_t)sm + 1023) & ~(uintptr_t)1023);
    char* STG = base + 131072;                 // staging region
    float* xchM = (float*)(base + 196608);     // [4][128]
    float* xchS = xchM + 512;                  // [4][128]

    int tid = threadIdx.x, w = tid >> 5, l = tid & 31;
    int wg = w >> 3, wl = w & 7, mg = wl >> 1, ng = wl & 1;   // P1/P5 mapping
    int smg = w >> 2, sng = w & 3;                            // P3/P4 mapping
    int p = blockIdx.x, b = p / NP1;
    const float* X  = pair_base(p, node, neigh);
    const float* W0 = Wv;
    const float* W1 = Wv + (size_t)128*HH;
    const float* P  = g_P + (size_t)b*TT*HH;

    // ---- Phase 1: Vt (8 pipelined slabs; 6-tile bufs at STG + b*49152) ----
    float accV[2][8][4];
    #pragma unroll
    for (int i=0;i<2;i++)
        #pragma unroll
        for (int j=0;j<8;j++){ accV[i][j][0]=accV[i][j][1]=accV[i][j][2]=accV[i][j][3]=0.f; }
    {
        float4 fW0[2], fW1[2], fX[2];
        ldg_slab_512(fW0, W0, HH, tid);
        ldg_slab_512(fW1, W1, HH, tid);
        ldg_slab_512(fX,  X,  HH, tid);
        cvt_sts_512(STG + 0*TILE32, STG + 1*TILE32, fW0, tid);
        cvt_sts_512(STG + 2*TILE32, STG + 3*TILE32, fW1, tid);
        cvt_sts_512(STG + 4*TILE32, STG + 5*TILE32, fX,  tid);
        ldg_slab_512(fW0, W0 + 32, HH, tid);
        ldg_slab_512(fW1, W1 + 32, HH, tid);
        ldg_slab_512(fX,  X  + 32, HH, tid);
        __syncthreads();

        #pragma unroll 2
        for (int s = 0; s < 8; ++s){
            char* cur = STG + (size_t)(s&1)*6*TILE32;
            uint32_t uA = smem_u32(cur) + (uint32_t)wg*2*TILE32;
            uint32_t uB = smem_u32(cur) + 4*TILE32;
            slab_mma32(accV, uA, uA + TILE32, uB, uB + TILE32, mg, ng, l);
            if (s < 7){
                char* nxt = STG + (size_t)((s+1)&1)*6*TILE32;
                cvt_sts_512(nxt + 0*TILE32, nxt + 1*TILE32, fW0, tid);
                cvt_sts_512(nxt + 2*TILE32, nxt + 3*TILE32, fW1, tid);
                cvt_sts_512(nxt + 4*TILE32, nxt + 5*TILE32, fX,  tid);
            }
            if (s < 6){
                ldg_slab_512(fW0, W0 + (s+2)*32, HH, tid);
                ldg_slab_512(fW1, W1 + (s+2)*32, HH, tid);
                ldg_slab_512(fX,  X  + (s+2)*32, HH, tid);
            }
            __syncthreads();
        }
    }

    // ---- Phase 2: Vt -> smem (old format) + stage S slab 0 into STG buf0 ----
    {
        float4 fP[2], fX[2];
        ldg_slab_512(fP, P, HH, tid);
        ldg_slab_512(fX, X, HH, tid);

        int q = l & 3, rb = l >> 2;
        char* VtBase = base + (size_t)wg*65536;
        char* th = VtBase + (ng ? 32768 : 0);
        char* tl = th + 16384;
        #pragma unroll
        for (int mt = 0; mt < 2; ++mt){
            #pragma unroll
            for (int hf = 0; hf < 2; ++hf){
                int c = 32*mg + 16*mt + 8*hf + rb;
                uint32_t swc = (uint32_t)(c & 7) << 4;
                #pragma unroll
                for (int nt = 0; nt < 8; ++nt){
                    int sl = nt*8 + q*2;
                    float a = accV[mt][nt][2*hf], bq = accV[mt][nt][2*hf+1];
                    uint32_t hi = pack_bf(a, bq);
                    float la = a  - __uint_as_float(hi << 16);
                    float lb = bq - __uint_as_float(hi & 0xffff0000u);
                    uint32_t lo = pack_bf(la, lb);
                    uint32_t boff = (uint32_t)c*128u + (uint32_t)sl*2u;
                    uint32_t swz = boff ^ swc;
                    *(uint32_t*)(th + swz) = hi;
                    *(uint32_t*)(tl + swz) = lo;
                }
            }
        }
        cvt_sts_512(STG + 0*TILE32, STG + 1*TILE32, fP, tid);
        cvt_sts_512(STG + 2*TILE32, STG + 3*TILE32, fX, tid);
        ldg_slab_512(fP, P + 32, HH, tid);
        ldg_slab_512(fX, X + 32, HH, tid);
        __syncthreads();

        // ---- Phase 3: S = P @ X^T (8 pipelined slabs; 4-tile bufs at STG + b*32768) ----
        float accS[2][4][4];
        #pragma unroll
        for (int i=0;i<2;i++)
            #pragma unroll
            for (int j=0;j<4;j++){ accS[i][j][0]=accS[i][j][1]=accS[i][j][2]=accS[i][j][3]=0.f; }

        #pragma unroll 2
        for (int s = 0; s < 8; ++s){
            char* cur = STG + (size_t)(s&1)*4*TILE32;
            uint32_t u = smem_u32(cur);
            slab_mma32_s(accS, u, u + TILE32, u + 2*TILE32, u + 3*TILE32, smg, sng, l);
            if (s < 7){
                char* nxt = STG + (size_t)((s+1)&1)*4*TILE32;
                cvt_sts_512(nxt + 0*TILE32, nxt + 1*TILE32, fP, tid);
                cvt_sts_512(nxt + 2*TILE32, nxt + 3*TILE32, fX, tid);
            }
            if (s < 6){
                ldg_slab_512(fP, P + (s+2)*32, HH, tid);
                ldg_slab_512(fX, X + (s+2)*32, HH, tid);
            }
            __syncthreads();
        }

        // ---- Phase 4: bias + softmax over 128 cols (combine 4 sng groups) ----
        int q4 = l & 3, rb4 = l >> 2;
        #pragma unroll
        for (int nt = 0; nt < 4; ++nt){
            float2 bb = *(const float2*)(bias + sng*32 + nt*8 + q4*2);
            #pragma unroll
            for (int mt = 0; mt < 2; ++mt){
                accS[mt][nt][0] += bb.x; accS[mt][nt][1] += bb.y;
                accS[mt][nt][2] += bb.x; accS[mt][nt][3] += bb.y;
            }
        }
        float mx[2][2];
        #pragma unroll
        for (int mt = 0; mt < 2; ++mt){
            mx[mt][0] = -1e30f; mx[mt][1] = -1e30f;
            #pragma unroll
            for (int nt = 0; nt < 4; ++nt){
                mx[mt][0] = fmaxf(mx[mt][0], fmaxf(accS[mt][nt][0], accS[mt][nt][1]));
                mx[mt][1] = fmaxf(mx[mt][1], fmaxf(accS[mt][nt][2], accS[mt][nt][3]));
            }
            #pragma unroll
            for (int o = 1; o <= 2; o <<= 1){
                mx[mt][0] = fmaxf(mx[mt][0], __shfl_xor_sync(0xffffffffu, mx[mt][0], o));
                mx[mt][1] = fmaxf(mx[mt][1], __shfl_xor_sync(0xffffffffu, mx[mt][1], o));
            }
        }
        if (q4 == 0){
            #pragma unroll
            for (int mt = 0; mt < 2; ++mt){
                xchM[sng*128 + 32*smg + 16*mt + rb4]     = mx[mt][0];
                xchM[sng*128 + 32*smg + 16*mt + 8 + rb4] = mx[mt][1];
            }
        }
        __syncthreads();
        float sum[2][2];
        #pragma unroll
        for (int mt = 0; mt < 2; ++mt){
            int r0 = 32*smg + 16*mt + rb4;
            float m0 = fmaxf(fmaxf(xchM[r0],       xchM[128 + r0]),
                             fmaxf(xchM[256 + r0], xchM[384 + r0]));
            float m1 = fmaxf(fmaxf(xchM[r0+8],       xchM[128 + r0+8]),
                             fmaxf(xchM[256 + r0+8], xchM[384 + r0+8]));
            sum[mt][0] = 0.f; sum[mt][1] = 0.f;
            #pragma unroll
            for (int nt = 0; nt < 4; ++nt){
                accS[mt][nt][0] = __expf(accS[mt][nt][0] - m0); sum[mt][0] += accS[mt][nt][0];
                accS[mt][nt][1] = __expf(accS[mt][nt][1] - m0); sum[mt][0] += accS[mt][nt][1];
                accS[mt][nt][2] = __expf(accS[mt][nt][2] - m1); sum[mt][1] += accS[mt][nt][2];
                accS[mt][nt][3] = __expf(accS[mt][nt][3] - m1); sum[mt][1] += accS[mt][nt][3];
            }
            #pragma unroll
            for (int o = 1; o <= 2; o <<= 1){
                sum[mt][0] += __shfl_xor_sync(0xffffffffu, sum[mt][0], o);
                sum[mt][1] += __shfl_xor_sync(0xffffffffu, sum[mt][1], o);
            }
        }
        if (q4 == 0){
            #pragma unroll
            for (int mt = 0; mt < 2; ++mt){
                xchS[sng*128 + 32*smg + 16*mt + rb4]     = sum[mt][0];
                xchS[sng*128 + 32*smg + 16*mt + 8 + rb4] = sum[mt][1];
            }
        }
        __syncthreads();
        // normalize; store A fp32 (if output) + A split tiles (new fmt) at STG
        float* Ap = Aout ? (Aout + (size_t)p*TT*TT) : nullptr;
        #pragma unroll
        for (int mt = 0; mt < 2; ++mt){
            int r0 = 32*smg + 16*mt + rb4, r1 = r0 + 8;
            float i0 = 1.f / (xchS[r0] + xchS[128+r0] + xchS[256+r0] + xchS[384+r0]);
            float i1 = 1.f / (xchS[r1] + xchS[128+r1] + xchS[256+r1] + xchS[384+r1]);
            char* th = STG + (size_t)sng*16384;      // A slab = sng (32 s-cols)
            char* tl = th + TILE32;
            uint32_t x0 = (((uint32_t)r0 >> 1) & 3u) << 4;
            uint32_t x1 = (((uint32_t)r1 >> 1) & 3u) << 4;
            #pragma unroll
            for (int nt = 0; nt < 4; ++nt){
                float a0 = accS[mt][nt][0]*i0, a1v = accS[mt][nt][1]*i0;
                float a2 = accS[mt][nt][2]*i1, a3v = accS[mt][nt][3]*i1;
                if (Ap){
                    *(float2*)(Ap + (size_t)r0*TT + sng*32 + nt*8 + q4*2) = make_float2(a0, a1v);
                    *(float2*)(Ap + (size_t)r1*TT + sng*32 + nt*8 + q4*2) = make_float2(a2, a3v);
                }
                uint32_t h0, l0, h1, l1;
                split2(a0, a1v, h0, l0);
                split2(a2, a3v, h1, l1);
                uint32_t cb = (uint32_t)(nt*8 + q4*2) * 2u;   // byte col within 32-col tile
                *(uint32_t*)(th + (uint32_t)r0*TPAD + (cb ^ x0)) = h0;
                *(uint32_t*)(tl + (uint32_t)r0*TPAD + (cb ^ x0)) = l0;
                *(uint32_t*)(th + (uint32_t)r1*TPAD + (cb ^ x1)) = h1;
                *(uint32_t*)(tl + (uint32_t)r1*TPAD + (cb ^ x1)) = l1;
            }
        }
    }
    __syncthreads();

    // ---- Phase 5: O = A @ Vt (4 slabs; everything resident, no staging, no syncs) ----
    float accO[2][8][4];
    #pragma unroll
    for (int i=0;i<2;i++)
        #pragma unroll
        for (int j=0;j<8;j++){ accO[i][j][0]=accO[i][j][1]=accO[i][j][2]=accO[i][j][3]=0.f; }

    #pragma unroll
    for (int ss = 0; ss < 4; ++ss){
        uint32_t uAH = smem_u32(STG + (size_t)ss*16384);
        uint32_t sb = (uint32_t)ss*32;
        uint32_t uBH = smem_u32(base + (size_t)wg*65536 + (sb < 64 ? 0 : 32768));
        slab_mma32_bold(accO, uAH, uAH + TILE32, uBH, uBH + 16384,
                        (sb & 63u)*2u, mg, ng, l);
    }

    // ---- store O[t, wg*128 + ng*64 + ...] ----
    {
        int q = l & 3, rb = l >> 2;
        float* Ob = Out + (size_t)p*TT*HH + wg*128;
        #pragma unroll
        for (int mt = 0; mt < 2; ++mt){
            int t0 = 32*mg + 16*mt + rb, t1 = t0 + 8;
            #pragma unroll
            for (int nt = 0; nt < 8; ++nt){
                *(float2*)(Ob + (size_t)t0*HH + ng*64 + nt*8 + q*2) =
                    make_float2(accO[mt][nt][0], accO[mt][nt][1]);
                *(float2*)(Ob + (size_t)t1*HH + ng*64 + nt*8 + q*2) =
                    make_float2(accO[mt][nt][2], accO[mt][nt][3]);
            }
        }
    }
}

// =========================================================================================
extern "C" void kernel_launch(void* const* d_in, const int* in_sizes, int n_in,
                              void* d_out, int out_size){
    const float* node  = (const float*)d_in[0];
    const float* neigh = (const float*)d_in[1];
    int w = (n_in >= 8) ? 2 : 1;
    const float* Wq = (const float*)d_in[w+1];
    const float* Wk = (const float*)d_in[w+2];
    const float* Wv = (const float*)d_in[w+3];
    const float* Wb = (const float*)d_in[w+4];
    const float* bv = (const float*)d_in[w+5];

    float* out = (float*)d_out;
    const long long O_ELEMS = (long long)NPAIRS*TT*HH;
    const long long A_ELEMS = (long long)NPAIRS*TT*TT;
    float* Aout = ((long long)out_size >= O_ELEMS + A_ELEMS) ? (out + O_ELEMS) : nullptr;

    const int ATT_SMEM = 131072 + 98304 + 1024;   // Vt + P1 staging + align = 230400 B
    cudaFuncSetAttribute(kernel_att, cudaFuncAttributeMaxDynamicSharedMemorySize, ATT_SMEM);

    sgemm_flat<0><<<dim3(64,2), 256>>>(node, Wq);        // g_q  = node @ Wq^T
    sgemm_flat<1><<<dim3(64,2), 256>>>(nullptr, Wb);     // g_t2 = g_q @ Wb
    sgemm_flat<2><<<dim3(64,2), 256>>>(nullptr, Wk);     // g_P  = g_t2 @ Wk
    kernel_att<<<dim3(NPAIRS,1), 512, ATT_SMEM>>>(node, neigh, Wv, bv, Aout, out);
}

// round 17
// speedup vs baseline: 1.5052x; 1.0045x over previous
#include <cuda_runtime.h>
#include <cstdint>

typedef unsigned long long ull;

#define BB 64
#define NN 16
#define TT 128
#define HH 256
#define NP1 17
#define NPAIRS (BB*NP1)   // 1088
#define LDT 132           // padded smem row stride for SIMT kernels
#define TPAD 64           // bytes/row of [128 x 32] bf16 tile; XOR ((row>>1)&3)<<4 -> conflict-free
#define TILE32 (128*TPAD) // 8192 B

// ---------------- scratch (static device globals; no runtime allocation) ----------------
__device__ float g_M1[HH*HH];        // Wq^T @ Wb
__device__ float g_M2[HH*HH];        // (Wq^T @ Wb) @ Wk
__device__ float g_P [BB*TT*HH];     // node @ M2

// =================== PTX helpers =========================================================
__device__ __forceinline__ uint32_t smem_u32(const void* p){
    uint32_t a;
    asm("{ .reg .u64 t; cvta.to.shared.u64 t, %1; cvt.u32.u64 %0, t; }" : "=r"(a) : "l"(p));
    return a;
}
__device__ __forceinline__ uint32_t pack_bf(float a, float b){
    uint32_t r;
    asm("cvt.rn.satfinite.bf16x2.f32 %0, %1, %2;" : "=r"(r) : "f"(b), "f"(a));
    return r;
}
__device__ __forceinline__ void split2(float x, float y, uint32_t& h, uint32_t& l){
    h = pack_bf(x, y);
    float lx = x - __uint_as_float(h << 16);
    float ly = y - __uint_as_float(h & 0xffff0000u);
    l = pack_bf(lx, ly);
}
__device__ __forceinline__ void ldsm4(uint32_t r[4], uint32_t addr){
    asm volatile("ldmatrix.sync.aligned.m8n8.x4.shared.b16 {%0,%1,%2,%3}, [%4];"
        : "=r"(r[0]), "=r"(r[1]), "=r"(r[2]), "=r"(r[3]) : "r"(addr));
}
__device__ __forceinline__ void mma_bf16(float c[4], const uint32_t a[4],
                                         uint32_t b0, uint32_t b1){
    asm volatile(
        "mma.sync.aligned.m16n8k16.row.col.f32.bf16.bf16.f32 "
        "{%0,%1,%2,%3}, {%4,%5,%6,%7}, {%8,%9}, {%0,%1,%2,%3};"
        : "+f"(c[0]), "+f"(c[1]), "+f"(c[2]), "+f"(c[3])
        : "r"(a[0]), "r"(a[1]), "r"(a[2]), "r"(a[3]), "r"(b0), "r"(b1));
}

__device__ __forceinline__ const float* pair_base(int p, const float* node, const float* neigh){
    int b = p / NP1, n = p % NP1;
    return (n == 0) ? node  + (size_t)b*TT*HH
                    : neigh + (size_t)(b*NN + (n-1))*TT*HH;
}

// ---------------- staging: [128x32] fp32 slab -> regs -> split bf16 tiles (TPAD=64+XOR) --
__device__ __forceinline__ void ldg_slab_512(float4 f[2], const float* __restrict__ src,
                                             int ld, int tid){
    int row = tid >> 2, c0 = (tid & 3) * 8;
    const float* s = src + (size_t)row*ld + c0;
    f[0] = *(const float4*)(s);
    f[1] = *(const float4*)(s + 4);
}
__device__ __forceinline__ void cvt_sts_512(char* th, char* tl, const float4 f[2], int tid){
    int row = tid >> 2;
    uint32_t c0 = (uint32_t)(tid & 3) * 16u;
    uint32_t xorv = (((uint32_t)row >> 1) & 3u) << 4;
    uint32_t h[4], l[4];
    split2(f[0].x, f[0].y, h[0], l[0]);
    split2(f[0].z, f[0].w, h[1], l[1]);
    split2(f[1].x, f[1].y, h[2], l[2]);
    split2(f[1].z, f[1].w, h[3], l[3]);
    *(uint4*)(th + row*TPAD + (c0 ^ xorv)) = make_uint4(h[0],h[1],h[2],h[3]);
    *(uint4*)(tl + row*TPAD + (c0 ^ xorv)) = make_uint4(l[0],l[1],l[2],l[3]);
}

// ---------------- K=32 slab of split MMAs, 32x64 warp tile (TPAD=64+XOR tiles) -----------
__device__ __forceinline__ void slab_mma32(float acc[2][8][4],
                                           uint32_t uAH, uint32_t uAL,
                                           uint32_t uBH, uint32_t uBL,
                                           int mg, int ng, int l){
    int r8 = l & 7;
    uint32_t xr = (((uint32_t)r8 >> 1) & 3u) << 4;
    uint32_t aKadd = ((l>>4)&1) * 16;
    int rowA0 = 32*mg + ((l>>3)&1)*8 + r8;
    int rowBl = ((l>>4)&1)*8 + r8;
    uint32_t bKadd = ((l>>3)&1) * 16;
    #pragma unroll
    for (int ks = 0; ks < 2; ++ks){
        uint32_t ah[2][4], al[2][4];
        #pragma unroll
        for (int mt = 0; mt < 2; ++mt){
            uint32_t aoff = (uint32_t)(rowA0 + 16*mt)*TPAD + (((uint32_t)ks*32 + aKadd) ^ xr);
            ldsm4(ah[mt], uAH + aoff);
            ldsm4(al[mt], uAL + aoff);
        }
        #pragma unroll
        for (int ntp = 0; ntp < 4; ++ntp){
            uint32_t boff = (uint32_t)(ng*64 + ntp*16 + rowBl)*TPAD
                          + (((uint32_t)ks*32 + bKadd) ^ xr);
            uint32_t bh[4], bl[4];
            ldsm4(bh, uBH + boff);
            ldsm4(bl, uBL + boff);
            #pragma unroll
            for (int mt = 0; mt < 2; ++mt){
                mma_bf16(acc[mt][2*ntp],   ah[mt], bh[0], bh[1]);
                mma_bf16(acc[mt][2*ntp],   ah[mt], bl[0], bl[1]);
                mma_bf16(acc[mt][2*ntp],   al[mt], bh[0], bh[1]);
                mma_bf16(acc[mt][2*ntp+1], ah[mt], bh[2], bh[3]);
                mma_bf16(acc[mt][2*ntp+1], ah[mt], bl[2], bl[3]);
                mma_bf16(acc[mt][2*ntp+1], al[mt], bh[2], bh[3]);
            }
        }
    }
}

// ---------------- K=32 slab, 32x32 warp tile (S phase; 4x4 warp grid) --------------------
__device__ __forceinline__ void slab_mma32_s(float acc[2][4][4],
                                             uint32_t uAH, uint32_t uAL,
                                             uint32_t uBH, uint32_t uBL,
                                             int smg, int sng, int l){
    int r8 = l & 7;
    uint32_t xr = (((uint32_t)r8 >> 1) & 3u) << 4;
    uint32_t aKadd = ((l>>4)&1) * 16;
    int rowA0 = 32*smg + ((l>>3)&1)*8 + r8;
    int rowBl = ((l>>4)&1)*8 + r8;
    uint32_t bKadd = ((l>>3)&1) * 16;
    #pragma unroll
    for (int ks = 0; ks < 2; ++ks){
        uint32_t ah[2][4], al[2][4];
        #pragma unroll
        for (int mt = 0; mt < 2; ++mt){
            uint32_t aoff = (uint32_t)(rowA0 + 16*mt)*TPAD + (((uint32_t)ks*32 + aKadd) ^ xr);
            ldsm4(ah[mt], uAH + aoff);
            ldsm4(al[mt], uAL + aoff);
        }
        #pragma unroll
        for (int ntp = 0; ntp < 2; ++ntp){
            uint32_t boff = (uint32_t)(sng*32 + ntp*16 + rowBl)*TPAD
                          + (((uint32_t)ks*32 + bKadd) ^ xr);
            uint32_t bh[4], bl[4];
            ldsm4(bh, uBH + boff);
            ldsm4(bl, uBL + boff);
            #pragma unroll
            for (int mt = 0; mt < 2; ++mt){
                mma_bf16(acc[mt][2*ntp],   ah[mt], bh[0], bh[1]);
                mma_bf16(acc[mt][2*ntp],   ah[mt], bl[0], bl[1]);
                mma_bf16(acc[mt][2*ntp],   al[mt], bh[0], bh[1]);
                mma_bf16(acc[mt][2*ntp+1], ah[mt], bh[2], bh[3]);
                mma_bf16(acc[mt][2*ntp+1], ah[mt], bl[2], bl[3]);
                mma_bf16(acc[mt][2*ntp+1], al[mt], bh[2], bh[3]);
            }
        }
    }
}

// ---------------- K=32 slab, A new-format / B OLD-format (128B rows + (r&7)<<4 XOR) ------
__device__ __forceinline__ void slab_mma32_bold(float acc[2][8][4],
                                                uint32_t uAH, uint32_t uAL,
                                                uint32_t uBH, uint32_t uBL, uint32_t srem2,
                                                int mg, int ng, int l){
    int r8 = l & 7;
    uint32_t xr = (((uint32_t)r8 >> 1) & 3u) << 4;
    uint32_t aKadd = ((l>>4)&1) * 16;
    int rowA0 = 32*mg + ((l>>3)&1)*8 + r8;
    int rowBl = ((l>>4)&1)*8 + r8;
    uint32_t bKadd = ((l>>3)&1) * 16;
    #pragma unroll
    for (int ks = 0; ks < 2; ++ks){
        uint32_t ah[2][4], al[2][4];
        #pragma unroll
        for (int mt = 0; mt < 2; ++mt){
            uint32_t aoff = (uint32_t)(rowA0 + 16*mt)*TPAD + (((uint32_t)ks*32 + aKadd) ^ xr);
            ldsm4(ah[mt], uAH + aoff);
            ldsm4(al[mt], uAL + aoff);
        }
        uint32_t kb = srem2 + (uint32_t)ks*32 + bKadd;
        #pragma unroll
        for (int ntp = 0; ntp < 4; ++ntp){
            int rowB = ng*64 + ntp*16 + rowBl;
            uint32_t boff = (uint32_t)rowB*128u + (kb ^ ((uint32_t)(rowB & 7) << 4));
            uint32_t bh[4], bl[4];
            ldsm4(bh, uBH + boff);
            ldsm4(bl, uBL + boff);
            #pragma unroll
            for (int mt = 0; mt < 2; ++mt){
                mma_bf16(acc[mt][2*ntp],   ah[mt], bh[0], bh[1]);
                mma_bf16(acc[mt][2*ntp],   ah[mt], bl[0], bl[1]);
                mma_bf16(acc[mt][2*ntp],   al[mt], bh[0], bh[1]);
                mma_bf16(acc[mt][2*ntp+1], ah[mt], bh[2], bh[3]);
                mma_bf16(acc[mt][2*ntp+1], ah[mt], bl[2], bl[3]);
                mma_bf16(acc[mt][2*ntp+1], al[mt], bh[2], bh[3]);
            }
        }
    }
}

// =================== SIMT fp32 machinery (weight-chain GEMMs) ============================
__device__ __forceinline__ void fma2(ull& d, ull a, ull b){
    asm("fma.rn.f32x2 %0, %1, %2, %0;" : "+l"(d) : "l"(a), "l"(b));
}
__device__ __forceinline__ ull pk2(float x, float y){
    ull r; asm("mov.b64 %0, {%1, %2};" : "=l"(r) : "f"(x), "f"(y)); return r;
}
__device__ __forceinline__ float2 upk(ull v){
    float2 f; asm("mov.b64 {%0, %1}, %2;" : "=f"(f.x), "=f"(f.y) : "l"(v)); return f;
}
struct F8 { float4 a, b; };
__device__ __forceinline__ F8 ldg_T(const float* __restrict__ src, int ld, int tid){
    int c4 = (tid & 3) * 4, r = tid >> 2;
    F8 f;
    f.a = *(const float4*)(src + (size_t)r*ld + c4);
    f.b = *(const float4*)(src + (size_t)(r+64)*ld + c4);
    return f;
}
__device__ __forceinline__ void sts_T(float (*dst)[LDT], F8 f, int tid){
    int c4 = (tid & 3) * 4, r = tid >> 2;
    dst[c4+0][r]    = f.a.x; dst[c4+1][r]    = f.a.y;
    dst[c4+2][r]    = f.a.z; dst[c4+3][r]    = f.a.w;
    dst[c4+0][r+64] = f.b.x; dst[c4+1][r+64] = f.b.y;
    dst[c4+2][r+64] = f.b.z; dst[c4+3][r+64] = f.b.w;
}
__device__ __forceinline__ F8 ldg_D(const float* __restrict__ src, int ld, int tid){
    int n4 = (tid & 15) * 4, k = tid >> 4;
    F8 f;
    f.a = *(const float4*)(src + (size_t)k*ld + n4);
    f.b = *(const float4*)(src + (size_t)k*ld + n4 + 64);
    return f;
}
__device__ __forceinline__ void sts_D(float (*dst)[LDT], F8 f, int tid){
    int n4 = (tid & 15) * 4, k = tid >> 4;
    *(float4*)(&dst[k][n4])      = f.a;
    *(float4*)(&dst[k][n4 + 64]) = f.b;
}
__device__ __forceinline__ void mm16(ull acc[8][4], const float (*As)[LDT],
                                     const float (*Bs)[LDT], int tx, int ty){
    #pragma unroll
    for (int k = 0; k < 16; ++k){
        float4 a0 = *(const float4*)(&As[k][ty*4]);
        float4 a1 = *(const float4*)(&As[k][64+ty*4]);
        float4 b0 = *(const float4*)(&Bs[k][tx*4]);
        float4 b1 = *(const float4*)(&Bs[k][64+tx*4]);
        ull bb0 = pk2(b0.x,b0.y), bb1 = pk2(b0.z,b0.w);
        ull bb2 = pk2(b1.x,b1.y), bb3 = pk2(b1.z,b1.w);
        float av[8] = {a0.x,a0.y,a0.z,a0.w,a1.x,a1.y,a1.z,a1.w};
        #pragma unroll
        for (int i = 0; i < 8; ++i){
            ull ad = pk2(av[i], av[i]);
            fma2(acc[i][0], ad, bb0);
            fma2(acc[i][1], ad, bb1);
            fma2(acc[i][2], ad, bb2);
            fma2(acc[i][3], ad, bb3);
        }
    }
}
__device__ __forceinline__ int row_of(int i, int ty){
    return (i < 4) ? (ty*4 + i) : (64 + ty*4 + (i-4));
}

// ================= Weight-chain GEMM: C = op(A) @ B, B always K-major ([K,N] row-major) ==
// ATRANS=1: A is [M,K] row-major (stage_T). ATRANS=0: A is [K,M] row-major -> op(A)=A^T
// (stage_D). C [M,N] row-major. K = HH = 256. Tiles 128x128, grid (M/128, N/128).
template<int ATRANS>
__global__ void __launch_bounds__(256, 2) gemm_nn(const float* __restrict__ A,
                                                  const float* __restrict__ B,
                                                  float* __restrict__ C){
    __shared__ __align__(16) float As[2][16][LDT], Bs[2][16][LDT];
    int tid = threadIdx.x, tx = tid & 15, ty = tid >> 4;
    int m0 = blockIdx.x * 128, n0 = blockIdx.y * 128;
    const float* Ab = ATRANS ? A + (size_t)m0*HH : A + m0;
    const float* Bb = B + n0;

    ull acc[8][4];
    #pragma unroll
    for (int i=0;i<8;i++){ acc[i][0]=acc[i][1]=acc[i][2]=acc[i][3]=0ULL; }

    F8 ra = ATRANS ? ldg_T(Ab, HH, tid) : ldg_D(Ab, HH, tid);
    F8 rb = ldg_D(Bb, HH, tid);
    if (ATRANS) sts_T(As[0], ra, tid); else sts_D(As[0], ra, tid);
    sts_D(Bs[0], rb, tid);
    __syncthreads();

    #pragma unroll 2
    for (int s = 0; s < 16; ++s){
        if (s < 15){
            ra = ATRANS ? ldg_T(Ab + (s+1)*16, HH, tid)
                        : ldg_D(Ab + (size_t)(s+1)*16*HH, HH, tid);
            rb = ldg_D(Bb + (size_t)(s+1)*16*HH, HH, tid);
        }
        mm16(acc, As[s&1], Bs[s&1], tx, ty);
        if (s < 15){
            if (ATRANS) sts_T(As[(s+1)&1], ra, tid); else sts_D(As[(s+1)&1], ra, tid);
            sts_D(Bs[(s+1)&1], rb, tid);
        }
        __syncthreads();
    }

    float* Cb = C + (size_t)m0*HH + n0;
    #pragma unroll
    for (int i=0;i<8;i++){
        int row = row_of(i, ty);
        float2 p0=upk(acc[i][0]), p1=upk(acc[i][1]), p2=upk(acc[i][2]), p3=upk(acc[i][3]);
        *(float4*)(Cb + (size_t)row*HH + tx*4)      = make_float4(p0.x,p0.y,p1.x,p1.y);
        *(float4*)(Cb + (size_t)row*HH + 64 + tx*4) = make_float4(p2.x,p2.y,p3.x,p3.y);
    }
}

// ================= FUSED attention kernel (512 threads, one CTA per pair) ================
// P1: Vt[c,s] = sum_h Wv[c,h] X[s,h]      (wg chunk split; staging @131072, 2x6 tiles)
// P2: Vt -> smem [0,131072) (old fmt)     (+ stage S slab 0)
// P3: S = P @ X^T                          (16 warps, 4x4 grid of 32x32; staging @131072)
// P4: softmax (4-group combine) -> A fp32 gmem (if output) + A split tiles @131072
// P5: O = A @ Vt                           (all operands resident; no staging, no syncs)
__global__ void __launch_bounds__(512, 1) kernel_att(const float* __restrict__ node,
                                                     const float* __restrict__ neigh,
                                                     const float* __restrict__ Wv,
                                                     const float* __restrict__ bias,
                                                     float* Aout,
                                                     float* __restrict__ Out){
    extern __shared__ char sm[];
    char* base = (char*)(((uintptr_t)sm + 1023) & ~(uintptr_t)1023);
    char* STG = base + 131072;                 // staging region
    float* xchM = (float*)(base + 196608);     // [4][128]
    float* xchS = xchM + 512;                  // [4][128]

    int tid = threadIdx.x, w = tid >> 5, l = tid & 31;
    int wg = w >> 3, wl = w & 7, mg = wl >> 1, ng = wl & 1;   // P1/P5 mapping
    int smg = w >> 2, sng = w & 3;                            // P3/P4 mapping
    int p = blockIdx.x, b = p / NP1;
    const float* X  = pair_base(p, node, neigh);
    const float* W0 = Wv;
    const float* W1 = Wv + (size_t)128*HH;
    const float* P  = g_P + (size_t)b*TT*HH;

    // ---- Phase 1: Vt (8 pipelined slabs; 6-tile bufs at STG + b*49152) ----
    float accV[2][8][4];
    #pragma unroll
    for (int i=0;i<2;i++)
        #pragma unroll
        for (int j=0;j<8;j++){ accV[i][j][0]=accV[i][j][1]=accV[i][j][2]=accV[i][j][3]=0.f; }
    {
        float4 fW0[2], fW1[2], fX[2];
        ldg_slab_512(fW0, W0, HH, tid);
        ldg_slab_512(fW1, W1, HH, tid);
        ldg_slab_512(fX,  X,  HH, tid);
        cvt_sts_512(STG + 0*TILE32, STG + 1*TILE32, fW0, tid);
        cvt_sts_512(STG + 2*TILE32, STG + 3*TILE32, fW1, tid);
        cvt_sts_512(STG + 4*TILE32, STG + 5*TILE32, fX,  tid);
        ldg_slab_512(fW0, W0 + 32, HH, tid);
        ldg_slab_512(fW1, W1 + 32, HH, tid);
        ldg_slab_512(fX,  X  + 32, HH, tid);
        __syncthreads();

        #pragma unroll 2
        for (int s = 0; s < 8; ++s){
            char* cur = STG + (size_t)(s&1)*6*TILE32;
            uint32_t uA = smem_u32(cur) + (uint32_t)wg*2*TILE32;
            uint32_t uB = smem_u32(cur) + 4*TILE32;
            slab_mma32(accV, uA, uA + TILE32, uB, uB + TILE32, mg, ng, l);
            if (s < 7){
                char* nxt = STG + (size_t)((s+1)&1)*6*TILE32;
                cvt_sts_512(nxt + 0*TILE32, nxt + 1*TILE32, fW0, tid);
                cvt_sts_512(nxt + 2*TILE32, nxt + 3*TILE32, fW1, tid);
                cvt_sts_512(nxt + 4*TILE32, nxt + 5*TILE32, fX,  tid);
            }
            if (s < 6){
                ldg_slab_512(fW0, W0 + (s+2)*32, HH, tid);
                ldg_slab_512(fW1, W1 + (s+2)*32, HH, tid);
                ldg_slab_512(fX,  X  + (s+2)*32, HH, tid);
            }
            __syncthreads();
        }
    }

    // ---- Phase 2: Vt -> smem (old format) + stage S slab 0 into STG buf0 ----
    {
        float4 fP[2], fX[2];
        ldg_slab_512(fP, P, HH, tid);
        ldg_slab_512(fX, X, HH, tid);

        int q = l & 3, rb = l >> 2;
        char* VtBase = base + (size_t)wg*65536;
        char* th = VtBase + (ng ? 32768 : 0);
        char* tl = th + 16384;
        #pragma unroll
        for (int mt = 0; mt < 2; ++mt){
            #pragma unroll
            for (int hf = 0; hf < 2; ++hf){
                int c = 32*mg + 16*mt + 8*hf + rb;
                uint32_t swc = (uint32_t)(c & 7) << 4;
                #pragma unroll
                for (int nt = 0; nt < 8; ++nt){
                    int sl = nt*8 + q*2;
                    float a = accV[mt][nt][2*hf], bq = accV[mt][nt][2*hf+1];
                    uint32_t hi = pack_bf(a, bq);
                    float la = a  - __uint_as_float(hi << 16);
                    float lb = bq - __uint_as_float(hi & 0xffff0000u);
                    uint32_t lo = pack_bf(la, lb);
                    uint32_t boff = (uint32_t)c*128u + (uint32_t)sl*2u;
                    uint32_t swz = boff ^ swc;
                    *(uint32_t*)(th + swz) = hi;
                    *(uint32_t*)(tl + swz) = lo;
                }
            }
        }
        cvt_sts_512(STG + 0*TILE32, STG + 1*TILE32, fP, tid);
        cvt_sts_512(STG + 2*TILE32, STG + 3*TILE32, fX, tid);
        ldg_slab_512(fP, P + 32, HH, tid);
        ldg_slab_512(fX, X + 32, HH, tid);
        __syncthreads();

        // ---- Phase 3: S = P @ X^T (8 pipelined slabs; 4-tile bufs at STG + b*32768) ----
        float accS[2][4][4];
        #pragma unroll
        for (int i=0;i<2;i++)
            #pragma unroll
            for (int j=0;j<4;j++){ accS[i][j][0]=accS[i][j][1]=accS[i][j][2]=accS[i][j][3]=0.f; }

        #pragma unroll 2
        for (int s = 0; s < 8; ++s){
            char* cur = STG + (size_t)(s&1)*4*TILE32;
            uint32_t u = smem_u32(cur);
            slab_mma32_s(accS, u, u + TILE32, u + 2*TILE32, u + 3*TILE32, smg, sng, l);
            if (s < 7){
                char* nxt = STG + (size_t)((s+1)&1)*4*TILE32;
                cvt_sts_512(nxt + 0*TILE32, nxt + 1*TILE32, fP, tid);
                cvt_sts_512(nxt + 2*TILE32, nxt + 3*TILE32, fX, tid);
            }
            if (s < 6){
                ldg_slab_512(fP, P + (s+2)*32, HH, tid);
                ldg_slab_512(fX, X + (s+2)*32, HH, tid);
            }
            __syncthreads();
        }

        // ---- Phase 4: bias + softmax over 128 cols (combine 4 sng groups) ----
        int q4 = l & 3, rb4 = l >> 2;
        #pragma unroll
        for (int nt = 0; nt < 4; ++nt){
            float2 bb = *(const float2*)(bias + sng*32 + nt*8 + q4*2);
            #pragma unroll
            for (int mt = 0; mt < 2; ++mt){
                accS[mt][nt][0] += bb.x; accS[mt][nt][1] += bb.y;
                accS[mt][nt][2] += bb.x; accS[mt][nt][3] += bb.y;
            }
        }
        float mx[2][2];
        #pragma unroll
        for (int mt = 0; mt < 2; ++mt){
            mx[mt][0] = -1e30f; mx[mt][1] = -1e30f;
            #pragma unroll
            for (int nt = 0; nt < 4; ++nt){
                mx[mt][0] = fmaxf(mx[mt][0], fmaxf(accS[mt][nt][0], accS[mt][nt][1]));
                mx[mt][1] = fmaxf(mx[mt][1], fmaxf(accS[mt][nt][2], accS[mt][nt][3]));
            }
            #pragma unroll
            for (int o = 1; o <= 2; o <<= 1){
                mx[mt][0] = fmaxf(mx[mt][0], __shfl_xor_sync(0xffffffffu, mx[mt][0], o));
                mx[mt][1] = fmaxf(mx[mt][1], __shfl_xor_sync(0xffffffffu, mx[mt][1], o));
            }
        }
        if (q4 == 0){
            #pragma unroll
            for (int mt = 0; mt < 2; ++mt){
                xchM[sng*128 + 32*smg + 16*mt + rb4]     = mx[mt][0];
                xchM[sng*128 + 32*smg + 16*mt + 8 + rb4] = mx[mt][1];
            }
        }
        __syncthreads();
        float sum[2][2];
        #pragma unroll
        for (int mt = 0; mt < 2; ++mt){
            int r0 = 32*smg + 16*mt + rb4;
            float m0 = fmaxf(fmaxf(xchM[r0],       xchM[128 + r0]),
                             fmaxf(xchM[256 + r0], xchM[384 + r0]));
            float m1 = fmaxf(fmaxf(xchM[r0+8],       xchM[128 + r0+8]),
                             fmaxf(xchM[256 + r0+8], xchM[384 + r0+8]));
            sum[mt][0] = 0.f; sum[mt][1] = 0.f;
            #pragma unroll
            for (int nt = 0; nt < 4; ++nt){
                accS[mt][nt][0] = __expf(accS[mt][nt][0] - m0); sum[mt][0] += accS[mt][nt][0];
                accS[mt][nt][1] = __expf(accS[mt][nt][1] - m0); sum[mt][0] += accS[mt][nt][1];
                accS[mt][nt][2] = __expf(accS[mt][nt][2] - m1); sum[mt][1] += accS[mt][nt][2];
                accS[mt][nt][3] = __expf(accS[mt][nt][3] - m1); sum[mt][1] += accS[mt][nt][3];
            }
            #pragma unroll
            for (int o = 1; o <= 2; o <<= 1){
                sum[mt][0] += __shfl_xor_sync(0xffffffffu, sum[mt][0], o);
                sum[mt][1] += __shfl_xor_sync(0xffffffffu, sum[mt][1], o);
            }
        }
        if (q4 == 0){
            #pragma unroll
            for (int mt = 0; mt < 2; ++mt){
                xchS[sng*128 + 32*smg + 16*mt + rb4]     = sum[mt][0];
                xchS[sng*128 + 32*smg + 16*mt + 8 + rb4] = sum[mt][1];
            }
        }
        __syncthreads();
        // normalize; store A fp32 (if output) + A split tiles (new fmt) at STG
        float* Ap = Aout ? (Aout + (size_t)p*TT*TT) : nullptr;
        #pragma unroll
        for (int mt = 0; mt < 2; ++mt){
            int r0 = 32*smg + 16*mt + rb4, r1 = r0 + 8;
            float i0 = 1.f / (xchS[r0] + xchS[128+r0] + xchS[256+r0] + xchS[384+r0]);
            float i1 = 1.f / (xchS[r1] + xchS[128+r1] + xchS[256+r1] + xchS[384+r1]);
            char* th = STG + (size_t)sng*16384;      // A slab = sng (32 s-cols)
            char* tl = th + TILE32;
            uint32_t x0 = (((uint32_t)r0 >> 1) & 3u) << 4;
            uint32_t x1 = (((uint32_t)r1 >> 1) & 3u) << 4;
            #pragma unroll
            for (int nt = 0; nt < 4; ++nt){
                float a0 = accS[mt][nt][0]*i0, a1v = accS[mt][nt][1]*i0;
                float a2 = accS[mt][nt][2]*i1, a3v = accS[mt][nt][3]*i1;
                if (Ap){
                    *(float2*)(Ap + (size_t)r0*TT + sng*32 + nt*8 + q4*2) = make_float2(a0, a1v);
                    *(float2*)(Ap + (size_t)r1*TT + sng*32 + nt*8 + q4*2) = make_float2(a2, a3v);
                }
                uint32_t h0, l0, h1, l1;
                split2(a0, a1v, h0, l0);
                split2(a2, a3v, h1, l1);
                uint32_t cb = (uint32_t)(nt*8 + q4*2) * 2u;   // byte col within 32-col tile
                *(uint32_t*)(th + (uint32_t)r0*TPAD + (cb ^ x0)) = h0;
                *(uint32_t*)(tl + (uint32_t)r0*TPAD + (cb ^ x0)) = l0;
                *(uint32_t*)(th + (uint32_t)r1*TPAD + (cb ^ x1)) = h1;
                *(uint32_t*)(tl + (uint32_t)r1*TPAD + (cb ^ x1)) = l1;
            }
        }
    }
    __syncthreads();

    // ---- Phase 5: O = A @ Vt (4 slabs; everything resident, no staging, no syncs) ----
    float accO[2][8][4];
    #pragma unroll
    for (int i=0;i<2;i++)
        #pragma unroll
        for (int j=0;j<8;j++){ accO[i][j][0]=accO[i][j][1]=accO[i][j][2]=accO[i][j][3]=0.f; }

    #pragma unroll
    for (int ss = 0; ss < 4; ++ss){
        uint32_t uAH = smem_u32(STG + (size_t)ss*16384);
        uint32_t sb = (uint32_t)ss*32;
        uint32_t uBH = smem_u32(base + (size_t)wg*65536 + (sb < 64 ? 0 : 32768));
        slab_mma32_bold(accO, uAH, uAH + TILE32, uBH, uBH + 16384,
                        (sb & 63u)*2u, mg, ng, l);
    }

    // ---- store O[t, wg*128 + ng*64 + ...] ----
    {
        int q = l & 3, rb = l >> 2;
        float* Ob = Out + (size_t)p*TT*HH + wg*128;
        #pragma unroll
        for (int mt = 0; mt < 2; ++mt){
            int t0 = 32*mg + 16*mt + rb, t1 = t0 + 8;
            #pragma unroll
            for (int nt = 0; nt < 8; ++nt){
                *(float2*)(Ob + (size_t)t0*HH + ng*64 + nt*8 + q*2) =
                    make_float2(accO[mt][nt][0], accO[mt][nt][1]);
                *(float2*)(Ob + (size_t)t1*HH + ng*64 + nt*8 + q*2) =
                    make_float2(accO[mt][nt][2], accO[mt][nt][3]);
            }
        }
    }
}

// =========================================================================================
extern "C" void kernel_launch(void* const* d_in, const int* in_sizes, int n_in,
                              void* d_out, int out_size){
    const float* node  = (const float*)d_in[0];
    const float* neigh = (const float*)d_in[1];
    int w = (n_in >= 8) ? 2 : 1;
    const float* Wq = (const float*)d_in[w+1];
    const float* Wk = (const float*)d_in[w+2];
    const float* Wv = (const float*)d_in[w+3];
    const float* Wb = (const float*)d_in[w+4];
    const float* bv = (const float*)d_in[w+5];

    float* out = (float*)d_out;
    const long long O_ELEMS = (long long)NPAIRS*TT*HH;
    const long long A_ELEMS = (long long)NPAIRS*TT*TT;
    float* Aout = ((long long)out_size >= O_ELEMS + A_ELEMS) ? (out + O_ELEMS) : nullptr;

    const int ATT_SMEM = 131072 + 98304 + 1024;   // Vt + P1 staging + align = 230400 B
    cudaFuncSetAttribute(kernel_att, cudaFuncAttributeMaxDynamicSharedMemorySize, ATT_SMEM);

    float* M1; cudaGetSymbolAddress((void**)&M1, g_M1);
    float* M2; cudaGetSymbolAddress((void**)&M2, g_M2);
    float* Pd; cudaGetSymbolAddress((void**)&Pd, g_P);

    // weight-chain folding: P = node @ (Wq^T @ Wb @ Wk)
    gemm_nn<0><<<dim3(2,2),  256>>>(Wq,   Wb, M1);   // M1 = Wq^T @ Wb   (A is [K,M])
    gemm_nn<1><<<dim3(2,2),  256>>>(M1,   Wk, M2);   // M2 = M1 @ Wk
    gemm_nn<1><<<dim3(64,2), 256>>>(node, M2, Pd);   // P  = node @ M2
    kernel_att<<<dim3(NPAIRS,1), 512, ATT_SMEM>>>(node, neigh, Wv, bv, Aout, out);
}